// round 12
// baseline (speedup 1.0000x reference)
#include <cuda_runtime.h>
#include <cuda_fp16.h>
#include <cstdint>

// ---------------------------------------------------------------------------
// VectorQuantize via mma.sync.m16n8k16.f16 (3xFP16 emulated fp32) + exact
// fp32 rescore. vq_main = R4 champion loop with early-issue cp.async
// ordering. Aux: float4 prep kernels, analytic total, fused finalize.
// ---------------------------------------------------------------------------

#define NCODES 8192
#define OFF_Q     0
#define OFF_IND   2097152
#define OFF_LOSS  2129920
#define OFF_NC    2129921
#define OFF_EA    2138113
#define OFF_NE    2662401
#define OUT_FULL  3186689

#define RPB    128
#define NTILES 64

// smem word offsets
#define W_AH   0        // [4 kc16][128 row][8 w] fp16x2 words
#define W_AL   4096
#define W_B    8192     // 2 stages x (hi 4096 + lo 4096)
#define W_CN   24576    // 2 x 128
#define W_IND  24832
#define W_RED  24960    // 2 halves x 128 float2
#define W_LOSS 25472
#define SMEM_TOTAL 101920

// device scratch
__device__ __align__(16) float g_pe[65536];
__device__ __align__(16) float g_cn[NCODES];
__device__ __align__(16) float g_counts[NCODES];
__device__ __align__(16) float g_esum[64 * NCODES];
__device__ __align__(16) float g_et[NCODES * 64];       // E^T fp32 [j][k]
__device__ __align__(16) uint32_t g_eh16[NCODES * 32];  // E^T fp16x2 hi [j][k/2]
__device__ __align__(16) uint32_t g_el16[NCODES * 32];  // E^T fp16x2 lo
__device__ float g_loss, g_total;

// ---------------------------------------------------------------------------
__device__ __forceinline__ uint32_t smem_u32(const void* p) {
    uint32_t a;
    asm("{ .reg .u64 t; cvta.to.shared.u64 t, %1; cvt.u32.u64 %0, t; }"
        : "=r"(a) : "l"(p));
    return a;
}
__device__ __forceinline__ void mma16(float* d, const uint32_t* a,
                                      uint32_t b0, uint32_t b1) {
    asm volatile(
        "mma.sync.aligned.m16n8k16.row.col.f32.f16.f16.f32 "
        "{%0,%1,%2,%3}, {%4,%5,%6,%7}, {%8,%9}, {%0,%1,%2,%3};"
        : "+f"(d[0]), "+f"(d[1]), "+f"(d[2]), "+f"(d[3])
        : "r"(a[0]), "r"(a[1]), "r"(a[2]), "r"(a[3]), "r"(b0), "r"(b1));
}
__device__ __forceinline__ void cp16(uint32_t dst, const void* src) {
    asm volatile("cp.async.cg.shared.global [%0], [%1], 16;"
                 :: "r"(dst), "l"(src) : "memory");
}
#define CP_COMMIT() asm volatile("cp.async.commit_group;" ::: "memory")
#define CP_WAIT1()  asm volatile("cp.async.wait_group 1;" ::: "memory")

__device__ __forceinline__ uint32_t pkh(float a, float b) {
    __half2 h = __floats2half2_rn(a, b);
    return *(uint32_t*)&h;
}

// ---------------------------------------------------------------------------
// prep0: float4 zero g_esum/g_counts, float4 PE build, cs-sum -> g_total.
// grid 512 x 256.
// ---------------------------------------------------------------------------
__global__ void vq_prep0(const float* __restrict__ pos_emb,
                         const float* __restrict__ cs) {
    const int tid = threadIdx.x;
    int i4 = blockIdx.x * 256 + tid;            // 0..131071 float4 units
    float4 z = make_float4(0.f, 0.f, 0.f, 0.f);
    ((float4*)g_esum)[i4] = z;
    if (i4 < 16384) {
        int idx = i4 * 4;
        int j = idx & 63, i = (idx >> 6) & 63, c = idx >> 12;
        int s = ((i >> 2) << 4) + (j >> 2);
        int d = (c << 4) + ((i & 3) << 2);      // (j&3)==0
        ((float4*)g_pe)[i4] = *(const float4*)(pos_emb + s * 256 + d);
    }
    if (i4 < 2048) ((float4*)g_counts)[i4] = z;

    if (blockIdx.x == 0) {
        float ssum = 0.0f;
#pragma unroll
        for (int q = 0; q < 8; q++) {
            float4 v = ((const float4*)cs)[tid + q * 256];
            ssum += v.x + v.y + v.z + v.w;
        }
        __shared__ float sh[256];
        sh[tid] = ssum;
        __syncthreads();
        for (int s = 128; s; s >>= 1) {
            if (tid < s) sh[tid] += sh[tid + s];
            __syncthreads();
        }
        if (tid == 0) {
            g_total = 0.8f * sh[0] + 0.2f * 32768.0f;
            g_loss = 0.0f;
        }
    }
}

// ---------------------------------------------------------------------------
// prep1: transpose embed -> g_et, fp16 hi/lo splits, code norms.
// grid 256 x 256 (block = 32 codes).
// ---------------------------------------------------------------------------
__global__ void vq_prep1(const float* __restrict__ embed) {
    __shared__ float sE[64][33];
    __shared__ float scn[32][8];
    const int tid = threadIdx.x;
    const int j0 = blockIdx.x * 32;
#pragma unroll
    for (int pass = 0; pass < 8; pass++) {
        int k = pass * 8 + (tid >> 5);
        int jl = tid & 31;
        sE[k][jl] = embed[(size_t)k * NCODES + j0 + jl];
    }
    __syncthreads();
    const int jl = tid & 31, p = tid >> 5;
    const int j = j0 + jl;
    float ssum = 0.0f;
#pragma unroll
    for (int w = 0; w < 4; w++) {
        int k = p * 8 + 2 * w;
        float v0 = sE[k][jl], v1 = sE[k + 1][jl];
        ssum += v0 * v0 + v1 * v1;
        *(float2*)(g_et + (size_t)j * 64 + k) = make_float2(v0, v1);
        __half h0 = __float2half_rn(v0), h1 = __float2half_rn(v1);
        float l0 = v0 - __half2float(h0), l1 = v1 - __half2float(h1);
        g_eh16[(size_t)j * 32 + (k >> 1)] =
            pkh(__half2float(h0), __half2float(h1));
        g_el16[(size_t)j * 32 + (k >> 1)] = pkh(l0, l1);
    }
    scn[jl][p] = ssum;
    __syncthreads();
    if (tid < 32) {
        float s = 0.0f;
#pragma unroll
        for (int q = 0; q < 8; q++) s += scn[tid][q];
        g_cn[j0 + tid] = -0.5f * s;
    }
}

// ---------------------------------------------------------------------------
// async B tile: g_eh16/g_el16 [j][k/2] -> smem [kc16][col][w] swizzled
// ---------------------------------------------------------------------------
__device__ __forceinline__ void load_b_tile(uint32_t smem_base, int t, int tid) {
    const int cb = t * 128;
    const uint32_t bb = smem_base + (uint32_t)(W_B + (t & 1) * 8192) * 4u;
#pragma unroll
    for (int i = 0; i < 8; i++) {
        int c = tid + (i << 8);             // 0..2047
        int arr = c >> 10;                  // 0 hi, 1 lo
        int rem = c & 1023;
        int j = rem >> 3, ch = rem & 7;     // ch: 16B chunk within 128B row
        int kc16 = ch >> 1, half8 = ch & 1;
        const uint32_t* src = (arr ? g_el16 : g_eh16) + (size_t)(cb + j) * 32 + ch * 4;
        uint32_t dstw = (uint32_t)(arr * 4096 + kc16 * 1024 + j * 8 +
                                   ((half8 ^ ((j >> 2) & 1)) << 2));
        cp16(bb + dstw * 4u, src);
    }
    if (tid < 32)
        cp16(smem_base + (uint32_t)(W_CN + (t & 1) * 128) * 4u + tid * 16,
             g_cn + cb + tid * 4);
}

// ---------------------------------------------------------------------------
// main: 256 CTAs x 256 threads, 2 CTAs/SM. warp tile 32x64, 3xFP16 mma.
// (R4 champion loop; cp.async issued ahead of independent ALU work)
// ---------------------------------------------------------------------------
__global__ void __launch_bounds__(256, 2)
vq_main(const float* __restrict__ input, float* __restrict__ out, int full) {
    extern __shared__ float smf[];
    const uint32_t smem_base = smem_u32(smf);
    const int tid = threadIdx.x, wid = tid >> 5, lane = tid & 31;
    const int wr = wid >> 1, wc = wid & 1;
    const int g = lane >> 2, kl = lane & 3;
    const int row0 = blockIdx.x * RPB;

    int* IndSh = (int*)(smf + W_IND);
    float2* RED = (float2*)(smf + W_RED);
    if (tid == 0) smf[W_LOSS] = 0.0f;

    // ---- issue B tiles 0/1 first: overlap gmem latency with A-build ----
    load_b_tile(smem_base, 0, tid); CP_COMMIT();
    load_b_tile(smem_base, 1, tid); CP_COMMIT();

    // ---- A build: X = input + pe, fp16 hi/lo, fragment-native layout ----
    {
        int row = tid >> 1, h = tid & 1, rg = row0 + row;
        const float4* ip = (const float4*)(input + (size_t)rg * 64);
        const float4* pp = (const float4*)(g_pe + (size_t)(rg & 1023) * 64);
        int swz = ((row >> 2) & 1) << 2;
#pragma unroll
        for (int i = 0; i < 8; i++) {
            int q = h * 8 + i;
            int k0 = 4 * q, kc16 = k0 >> 4, o = k0 & 15, w = o >> 1;
            float4 a = ip[q], b = pp[q];
            float x0 = a.x + b.x, x1 = a.y + b.y;
            float x2 = a.z + b.z, x3 = a.w + b.w;
            __half h0 = __float2half_rn(x0), h1 = __float2half_rn(x1);
            __half h2 = __float2half_rn(x2), h3 = __float2half_rn(x3);
            float l0 = x0 - __half2float(h0), l1 = x1 - __half2float(h1);
            float l2 = x2 - __half2float(h2), l3 = x3 - __half2float(h3);
            int wsw = w ^ swz;
            int off = kc16 * 1024 + row * 8 + wsw;
            *(uint2*)(smf + W_AH + off) =
                make_uint2(pkh(__half2float(h0), __half2float(h1)),
                           pkh(__half2float(h2), __half2float(h3)));
            *(uint2*)(smf + W_AL + off) = make_uint2(pkh(l0, l1), pkh(l2, l3));
        }
    }

    float best[4];
    int bcol[4];
#pragma unroll
    for (int s = 0; s < 4; s++) { best[s] = -3.4e38f; bcol[s] = 0; }

    const uint32_t* AH = (const uint32_t*)(smf + W_AH);
    const uint32_t* ALp = (const uint32_t*)(smf + W_AL);
    const int aswz = ((g >> 2) & 1) << 2;
    const int w0 = kl ^ aswz, w1 = (kl + 4) ^ aswz;

    for (int t = 0; t < NTILES; t++) {
        CP_WAIT1();
        __syncthreads();
        const uint32_t* BH = (const uint32_t*)(smf + W_B + (t & 1) * 8192);
        const uint32_t* BL = BH + 4096;
        const float* cn = smf + W_CN + (t & 1) * 128 + wc * 64;

        float acc[2][8][4];
#pragma unroll
        for (int nf = 0; nf < 8; nf++) {
            float c0 = cn[nf * 8 + 2 * kl];
            float c1 = cn[nf * 8 + 2 * kl + 1];
#pragma unroll
            for (int m = 0; m < 2; m++) {
                acc[m][nf][0] = c0; acc[m][nf][1] = c1;
                acc[m][nf][2] = c0; acc[m][nf][3] = c1;
            }
        }
#pragma unroll
        for (int kc16 = 0; kc16 < 4; kc16++) {
            uint32_t ah[2][4], al[2][4];
#pragma unroll
            for (int m = 0; m < 2; m++) {
                int base = kc16 * 1024 + (wr * 32 + m * 16 + g) * 8;
                ah[m][0] = AH[base + w0];      ah[m][1] = AH[base + 64 + w0];
                ah[m][2] = AH[base + w1];      ah[m][3] = AH[base + 64 + w1];
                al[m][0] = ALp[base + w0];     al[m][1] = ALp[base + 64 + w0];
                al[m][2] = ALp[base + w1];     al[m][3] = ALp[base + 64 + w1];
            }
#pragma unroll
            for (int nf = 0; nf < 8; nf++) {
                int bb = kc16 * 1024 + (wc * 64 + nf * 8 + g) * 8;
                uint32_t bh0 = BH[bb + w0], bh1 = BH[bb + w1];
                uint32_t bl0 = BL[bb + w0], bl1 = BL[bb + w1];
#pragma unroll
                for (int m = 0; m < 2; m++) {
                    mma16(acc[m][nf], ah[m], bh0, bh1);
                    mma16(acc[m][nf], ah[m], bl0, bl1);
                    mma16(acc[m][nf], al[m], bh0, bh1);
                }
            }
        }
        // release the stage and issue next loads BEFORE register-only argmax
        __syncthreads();
        if (t + 2 < NTILES) load_b_tile(smem_base, t + 2, tid);
        CP_COMMIT();

        // running per-slot argmax (ascending cols -> strict > keeps low index)
        int colbase0 = t * 128 + wc * 64 + 2 * kl;
#pragma unroll
        for (int m = 0; m < 2; m++) {
#pragma unroll
            for (int nf = 0; nf < 8; nf++) {
                int c01 = colbase0 + nf * 8;
                float v0 = acc[m][nf][0], v1 = acc[m][nf][1];
                float v2 = acc[m][nf][2], v3 = acc[m][nf][3];
                int s0 = 2 * m, s1 = 2 * m + 1;
                if (v0 > best[s0]) { best[s0] = v0; bcol[s0] = c01; }
                if (v1 > best[s0]) { best[s0] = v1; bcol[s0] = c01 + 1; }
                if (v2 > best[s1]) { best[s1] = v2; bcol[s1] = c01; }
                if (v3 > best[s1]) { best[s1] = v3; bcol[s1] = c01 + 1; }
            }
        }
    }

    // ---- quad reduce ----
#pragma unroll
    for (int s = 0; s < 4; s++) {
        float v = best[s];
        int c = bcol[s];
#pragma unroll
        for (int off = 1; off <= 2; off <<= 1) {
            float ov = __shfl_xor_sync(0xffffffffu, v, off);
            int oc = __shfl_xor_sync(0xffffffffu, c, off);
            if (ov > v || (ov == v && oc < c)) { v = ov; c = oc; }
        }
        if ((lane & 3) == 0) {
            int rowl = wr * 32 + (s >> 1) * 16 + (s & 1) * 8 + g;
            RED[wc * 128 + rowl] = make_float2(v, __int_as_float(c));
        }
    }
    __syncthreads();

    // ---- exact fp32 rescore of the two half-winners per row ----
    if (tid < 128) {
        int row = tid, rg = row0 + row;
        float xv[64];
        const float4* ip = (const float4*)(input + (size_t)rg * 64);
        const float4* pp = (const float4*)(g_pe + (size_t)(rg & 1023) * 64);
#pragma unroll
        for (int q = 0; q < 16; q++) {
            float4 a = ip[q], b = pp[q];
            xv[q * 4 + 0] = a.x + b.x; xv[q * 4 + 1] = a.y + b.y;
            xv[q * 4 + 2] = a.z + b.z; xv[q * 4 + 3] = a.w + b.w;
        }
        int c0 = __float_as_int(RED[row].y);
        int c1 = __float_as_int(RED[128 + row].y);
        float s0 = g_cn[c0], s1 = g_cn[c1];
        const float4* e0 = (const float4*)(g_et + (size_t)c0 * 64);
        const float4* e1 = (const float4*)(g_et + (size_t)c1 * 64);
#pragma unroll
        for (int q = 0; q < 16; q++) {
            float4 ea = e0[q], eb = e1[q];
            s0 = fmaf(xv[q * 4 + 0], ea.x, s0); s0 = fmaf(xv[q * 4 + 1], ea.y, s0);
            s0 = fmaf(xv[q * 4 + 2], ea.z, s0); s0 = fmaf(xv[q * 4 + 3], ea.w, s0);
            s1 = fmaf(xv[q * 4 + 0], eb.x, s1); s1 = fmaf(xv[q * 4 + 1], eb.y, s1);
            s1 = fmaf(xv[q * 4 + 2], eb.z, s1); s1 = fmaf(xv[q * 4 + 3], eb.w, s1);
        }
        int bj = (s1 > s0 || (s1 == s0 && c1 < c0)) ? c1 : c0;
        IndSh[row] = bj;
        if (full) out[OFF_IND + rg] = (float)bj;
        atomicAdd(&g_counts[bj], 1.0f);
    }
    __syncthreads();

    // ---- epilogue: quantize gather, loss, embed_sum scatter ----
    {
        float lsum = 0.0f;
        for (int it = 0; it < 16; it++) {
            int rloc = wid * 16 + it;
            int rg = row0 + rloc;
            int j = IndSh[rloc];
#pragma unroll
            for (int h2 = 0; h2 < 2; h2++) {
                int k = lane + 32 * h2;
                float ev = g_et[(size_t)j * 64 + k];
                float iv = input[(size_t)rg * 64 + k];
                float dd = ev - iv;
                lsum += dd * dd;
                out[OFF_Q + (size_t)rg * 64 + k] = ev;
                float xv2 = iv + g_pe[(rg & 1023) * 64 + k];
                atomicAdd(&g_esum[(size_t)k * NCODES + j], xv2);
            }
        }
#pragma unroll
        for (int off = 16; off; off >>= 1)
            lsum += __shfl_down_sync(0xffffffffu, lsum, off);
        if (lane == 0) atomicAdd(smf + W_LOSS, lsum);
    }
    __syncthreads();
    if (tid == 0) atomicAdd(&g_loss, smf[W_LOSS]);
}

// ---------------------------------------------------------------------------
// fused finalize: new_cluster, new_embed_avg, new_embed, loss.
// grid 512 x 256 (float4 loads; scalar stores — out offsets are odd).
// ---------------------------------------------------------------------------
__global__ void vq_fin(const float* __restrict__ cs,
                       const float* __restrict__ ea,
                       float* __restrict__ out) {
    int i4 = blockIdx.x * 256 + threadIdx.x;    // 0..131071
    int idx = i4 * 4;
    float4 e4 = ((const float4*)ea)[i4];
    float4 s4 = ((const float4*)g_esum)[i4];
    float nea0 = 0.8f * e4.x + 0.2f * s4.x;
    float nea1 = 0.8f * e4.y + 0.2f * s4.y;
    float nea2 = 0.8f * e4.z + 0.2f * s4.z;
    float nea3 = 0.8f * e4.w + 0.2f * s4.w;
    out[OFF_EA + idx + 0] = nea0;
    out[OFF_EA + idx + 1] = nea1;
    out[OFF_EA + idx + 2] = nea2;
    out[OFF_EA + idx + 3] = nea3;

    int jb = (idx & (NCODES - 1)) >> 2;
    float4 c4 = ((const float4*)cs)[jb];
    float4 t4 = ((const float4*)g_counts)[jb];
    float nc0 = 0.8f * c4.x + 0.2f * t4.x;
    float nc1 = 0.8f * c4.y + 0.2f * t4.y;
    float nc2 = 0.8f * c4.z + 0.2f * t4.z;
    float nc3 = 0.8f * c4.w + 0.2f * t4.w;

    float total = g_total;
    float denom = total + NCODES * 1e-5f;
    float sc = total / denom;
    out[OFF_NE + idx + 0] = nea0 / ((nc0 + 1e-5f) * sc);
    out[OFF_NE + idx + 1] = nea1 / ((nc1 + 1e-5f) * sc);
    out[OFF_NE + idx + 2] = nea2 / ((nc2 + 1e-5f) * sc);
    out[OFF_NE + idx + 3] = nea3 / ((nc3 + 1e-5f) * sc);

    if (idx < NCODES) {
        out[OFF_NC + idx + 0] = nc0;
        out[OFF_NC + idx + 1] = nc1;
        out[OFF_NC + idx + 2] = nc2;
        out[OFF_NC + idx + 3] = nc3;
    }
    if (i4 == 0) out[OFF_LOSS] = g_loss * (1.0f / 2097152.0f);
}

// ---------------------------------------------------------------------------
extern "C" void kernel_launch(void* const* d_in, const int* in_sizes, int n_in,
                              void* d_out, int out_size) {
    const float* input = (const float*)d_in[0];
    const float* embed = (const float*)d_in[1];
    const float* pos   = (const float*)d_in[2];
    const float* cs    = (const float*)d_in[3];
    const float* ea    = (const float*)d_in[4];
    float* out = (float*)d_out;

    cudaFuncSetAttribute(vq_main, cudaFuncAttributeMaxDynamicSharedMemorySize,
                         SMEM_TOTAL);
    int full = (out_size >= OUT_FULL) ? 1 : 0;

    vq_prep0<<<512, 256>>>(pos, cs);
    vq_prep1<<<256, 256>>>(embed);
    vq_main<<<256, 256, SMEM_TOTAL>>>(input, out, full);
    if (full) vq_fin<<<512, 256>>>(cs, ea, out);
}

// round 13
// speedup vs baseline: 1.0296x; 1.0296x over previous
#include <cuda_runtime.h>
#include <cuda_fp16.h>
#include <cstdint>

// ---------------------------------------------------------------------------
// VectorQuantize via mma.sync.m16n8k16.f16 (3xFP16 emulated fp32) + exact
// fp32 rescore. vq_main = R4 champion verbatim. Aux kernels consolidated:
// analytic total (counts sum == 32768 exactly) kills fin1; float4 prep.
// (R10 champion configuration, 346.2 us.)
// ---------------------------------------------------------------------------

#define NCODES 8192
#define OFF_Q     0
#define OFF_IND   2097152
#define OFF_LOSS  2129920
#define OFF_NC    2129921
#define OFF_EA    2138113
#define OFF_NE    2662401
#define OUT_FULL  3186689

#define RPB    128
#define NTILES 64

// smem word offsets
#define W_AH   0        // [4 kc16][128 row][8 w] fp16x2 words
#define W_AL   4096
#define W_B    8192     // 2 stages x (hi 4096 + lo 4096)
#define W_CN   24576    // 2 x 128
#define W_IND  24832
#define W_RED  24960    // 2 halves x 128 float2
#define W_LOSS 25472
#define SMEM_TOTAL 101920

// device scratch
__device__ __align__(16) float g_pe[65536];
__device__ __align__(16) float g_cn[NCODES];
__device__ __align__(16) float g_counts[NCODES];
__device__ __align__(16) float g_esum[64 * NCODES];
__device__ __align__(16) float g_et[NCODES * 64];       // E^T fp32 [j][k]
__device__ __align__(16) uint32_t g_eh16[NCODES * 32];  // E^T fp16x2 hi [j][k/2]
__device__ __align__(16) uint32_t g_el16[NCODES * 32];  // E^T fp16x2 lo
__device__ float g_loss, g_total;

// ---------------------------------------------------------------------------
__device__ __forceinline__ uint32_t smem_u32(const void* p) {
    uint32_t a;
    asm("{ .reg .u64 t; cvta.to.shared.u64 t, %1; cvt.u32.u64 %0, t; }"
        : "=r"(a) : "l"(p));
    return a;
}
__device__ __forceinline__ void mma16(float* d, const uint32_t* a,
                                      uint32_t b0, uint32_t b1) {
    asm volatile(
        "mma.sync.aligned.m16n8k16.row.col.f32.f16.f16.f32 "
        "{%0,%1,%2,%3}, {%4,%5,%6,%7}, {%8,%9}, {%0,%1,%2,%3};"
        : "+f"(d[0]), "+f"(d[1]), "+f"(d[2]), "+f"(d[3])
        : "r"(a[0]), "r"(a[1]), "r"(a[2]), "r"(a[3]), "r"(b0), "r"(b1));
}
__device__ __forceinline__ void cp16(uint32_t dst, const void* src) {
    asm volatile("cp.async.cg.shared.global [%0], [%1], 16;"
                 :: "r"(dst), "l"(src) : "memory");
}
#define CP_COMMIT() asm volatile("cp.async.commit_group;" ::: "memory")
#define CP_WAIT1()  asm volatile("cp.async.wait_group 1;" ::: "memory")

__device__ __forceinline__ uint32_t pkh(float a, float b) {
    __half2 h = __floats2half2_rn(a, b);
    return *(uint32_t*)&h;
}

// ---------------------------------------------------------------------------
// prep0: float4 zero g_esum/g_counts, float4 PE build, cs-sum -> g_total.
// grid 512 x 256.
// ---------------------------------------------------------------------------
__global__ void vq_prep0(const float* __restrict__ pos_emb,
                         const float* __restrict__ cs) {
    const int tid = threadIdx.x;
    int i4 = blockIdx.x * 256 + tid;            // 0..131071 float4 units
    float4 z = make_float4(0.f, 0.f, 0.f, 0.f);
    ((float4*)g_esum)[i4] = z;
    if (i4 < 16384) {
        int idx = i4 * 4;
        int j = idx & 63, i = (idx >> 6) & 63, c = idx >> 12;
        int s = ((i >> 2) << 4) + (j >> 2);
        int d = (c << 4) + ((i & 3) << 2);      // (j&3)==0
        ((float4*)g_pe)[i4] = *(const float4*)(pos_emb + s * 256 + d);
    }
    if (i4 < 2048) ((float4*)g_counts)[i4] = z;

    if (blockIdx.x == 0) {
        float ssum = 0.0f;
#pragma unroll
        for (int q = 0; q < 8; q++) {
            float4 v = ((const float4*)cs)[tid + q * 256];
            ssum += v.x + v.y + v.z + v.w;
        }
        __shared__ float sh[256];
        sh[tid] = ssum;
        __syncthreads();
        for (int s = 128; s; s >>= 1) {
            if (tid < s) sh[tid] += sh[tid + s];
            __syncthreads();
        }
        if (tid == 0) {
            g_total = 0.8f * sh[0] + 0.2f * 32768.0f;
            g_loss = 0.0f;
        }
    }
}

// ---------------------------------------------------------------------------
// prep1: transpose embed -> g_et, fp16 hi/lo splits, code norms.
// grid 256 x 256 (block = 32 codes).
// ---------------------------------------------------------------------------
__global__ void vq_prep1(const float* __restrict__ embed) {
    __shared__ float sE[64][33];
    __shared__ float scn[32][8];
    const int tid = threadIdx.x;
    const int j0 = blockIdx.x * 32;
#pragma unroll
    for (int pass = 0; pass < 8; pass++) {
        int k = pass * 8 + (tid >> 5);
        int jl = tid & 31;
        sE[k][jl] = embed[(size_t)k * NCODES + j0 + jl];
    }
    __syncthreads();
    const int jl = tid & 31, p = tid >> 5;
    const int j = j0 + jl;
    float ssum = 0.0f;
#pragma unroll
    for (int w = 0; w < 4; w++) {
        int k = p * 8 + 2 * w;
        float v0 = sE[k][jl], v1 = sE[k + 1][jl];
        ssum += v0 * v0 + v1 * v1;
        *(float2*)(g_et + (size_t)j * 64 + k) = make_float2(v0, v1);
        __half h0 = __float2half_rn(v0), h1 = __float2half_rn(v1);
        float l0 = v0 - __half2float(h0), l1 = v1 - __half2float(h1);
        g_eh16[(size_t)j * 32 + (k >> 1)] =
            pkh(__half2float(h0), __half2float(h1));
        g_el16[(size_t)j * 32 + (k >> 1)] = pkh(l0, l1);
    }
    scn[jl][p] = ssum;
    __syncthreads();
    if (tid < 32) {
        float s = 0.0f;
#pragma unroll
        for (int q = 0; q < 8; q++) s += scn[tid][q];
        g_cn[j0 + tid] = -0.5f * s;
    }
}

// ---------------------------------------------------------------------------
// async B tile: g_eh16/g_el16 [j][k/2] -> smem [kc16][col][w] swizzled
// ---------------------------------------------------------------------------
__device__ __forceinline__ void load_b_tile(uint32_t smem_base, int t, int tid) {
    const int cb = t * 128;
    const uint32_t bb = smem_base + (uint32_t)(W_B + (t & 1) * 8192) * 4u;
#pragma unroll
    for (int i = 0; i < 8; i++) {
        int c = tid + (i << 8);             // 0..2047
        int arr = c >> 10;                  // 0 hi, 1 lo
        int rem = c & 1023;
        int j = rem >> 3, ch = rem & 7;     // ch: 16B chunk within 128B row
        int kc16 = ch >> 1, half8 = ch & 1;
        const uint32_t* src = (arr ? g_el16 : g_eh16) + (size_t)(cb + j) * 32 + ch * 4;
        uint32_t dstw = (uint32_t)(arr * 4096 + kc16 * 1024 + j * 8 +
                                   ((half8 ^ ((j >> 2) & 1)) << 2));
        cp16(bb + dstw * 4u, src);
    }
    if (tid < 32)
        cp16(smem_base + (uint32_t)(W_CN + (t & 1) * 128) * 4u + tid * 16,
             g_cn + cb + tid * 4);
}

// ---------------------------------------------------------------------------
// main: 256 CTAs x 256 threads, 2 CTAs/SM. warp tile 32x64, 3xFP16 mma.
// (R4 champion, verbatim)
// ---------------------------------------------------------------------------
__global__ void __launch_bounds__(256, 2)
vq_main(const float* __restrict__ input, float* __restrict__ out, int full) {
    extern __shared__ float smf[];
    const uint32_t smem_base = smem_u32(smf);
    const int tid = threadIdx.x, wid = tid >> 5, lane = tid & 31;
    const int wr = wid >> 1, wc = wid & 1;
    const int g = lane >> 2, kl = lane & 3;
    const int row0 = blockIdx.x * RPB;

    int* IndSh = (int*)(smf + W_IND);
    float2* RED = (float2*)(smf + W_RED);
    if (tid == 0) smf[W_LOSS] = 0.0f;

    // ---- A build: X = input + pe, fp16 hi/lo, fragment-native layout ----
    {
        int row = tid >> 1, h = tid & 1, rg = row0 + row;
        const float4* ip = (const float4*)(input + (size_t)rg * 64);
        const float4* pp = (const float4*)(g_pe + (size_t)(rg & 1023) * 64);
        int swz = ((row >> 2) & 1) << 2;
#pragma unroll
        for (int i = 0; i < 8; i++) {
            int q = h * 8 + i;
            int k0 = 4 * q, kc16 = k0 >> 4, o = k0 & 15, w = o >> 1;
            float4 a = ip[q], b = pp[q];
            float x0 = a.x + b.x, x1 = a.y + b.y;
            float x2 = a.z + b.z, x3 = a.w + b.w;
            __half h0 = __float2half_rn(x0), h1 = __float2half_rn(x1);
            __half h2 = __float2half_rn(x2), h3 = __float2half_rn(x3);
            float l0 = x0 - __half2float(h0), l1 = x1 - __half2float(h1);
            float l2 = x2 - __half2float(h2), l3 = x3 - __half2float(h3);
            int wsw = w ^ swz;
            int off = kc16 * 1024 + row * 8 + wsw;
            *(uint2*)(smf + W_AH + off) =
                make_uint2(pkh(__half2float(h0), __half2float(h1)),
                           pkh(__half2float(h2), __half2float(h3)));
            *(uint2*)(smf + W_AL + off) = make_uint2(pkh(l0, l1), pkh(l2, l3));
        }
    }
    load_b_tile(smem_base, 0, tid); CP_COMMIT();
    load_b_tile(smem_base, 1, tid); CP_COMMIT();

    float best[4];
    int bcol[4];
#pragma unroll
    for (int s = 0; s < 4; s++) { best[s] = -3.4e38f; bcol[s] = 0; }

    const uint32_t* AH = (const uint32_t*)(smf + W_AH);
    const uint32_t* ALp = (const uint32_t*)(smf + W_AL);
    const int aswz = ((g >> 2) & 1) << 2;
    const int w0 = kl ^ aswz, w1 = (kl + 4) ^ aswz;

    for (int t = 0; t < NTILES; t++) {
        CP_WAIT1();
        __syncthreads();
        const uint32_t* BH = (const uint32_t*)(smf + W_B + (t & 1) * 8192);
        const uint32_t* BL = BH + 4096;
        const float* cn = smf + W_CN + (t & 1) * 128 + wc * 64;

        float acc[2][8][4];
#pragma unroll
        for (int nf = 0; nf < 8; nf++) {
            float c0 = cn[nf * 8 + 2 * kl];
            float c1 = cn[nf * 8 + 2 * kl + 1];
#pragma unroll
            for (int m = 0; m < 2; m++) {
                acc[m][nf][0] = c0; acc[m][nf][1] = c1;
                acc[m][nf][2] = c0; acc[m][nf][3] = c1;
            }
        }
#pragma unroll
        for (int kc16 = 0; kc16 < 4; kc16++) {
            uint32_t ah[2][4], al[2][4];
#pragma unroll
            for (int m = 0; m < 2; m++) {
                int base = kc16 * 1024 + (wr * 32 + m * 16 + g) * 8;
                ah[m][0] = AH[base + w0];      ah[m][1] = AH[base + 64 + w0];
                ah[m][2] = AH[base + w1];      ah[m][3] = AH[base + 64 + w1];
                al[m][0] = ALp[base + w0];     al[m][1] = ALp[base + 64 + w0];
                al[m][2] = ALp[base + w1];     al[m][3] = ALp[base + 64 + w1];
            }
#pragma unroll
            for (int nf = 0; nf < 8; nf++) {
                int bb = kc16 * 1024 + (wc * 64 + nf * 8 + g) * 8;
                uint32_t bh0 = BH[bb + w0], bh1 = BH[bb + w1];
                uint32_t bl0 = BL[bb + w0], bl1 = BL[bb + w1];
#pragma unroll
                for (int m = 0; m < 2; m++) {
                    mma16(acc[m][nf], ah[m], bh0, bh1);
                    mma16(acc[m][nf], ah[m], bl0, bl1);
                    mma16(acc[m][nf], al[m], bh0, bh1);
                }
            }
        }
        // running per-slot argmax (ascending cols -> strict > keeps low index)
        int colbase0 = t * 128 + wc * 64 + 2 * kl;
#pragma unroll
        for (int m = 0; m < 2; m++) {
#pragma unroll
            for (int nf = 0; nf < 8; nf++) {
                int c01 = colbase0 + nf * 8;
                float v0 = acc[m][nf][0], v1 = acc[m][nf][1];
                float v2 = acc[m][nf][2], v3 = acc[m][nf][3];
                int s0 = 2 * m, s1 = 2 * m + 1;
                if (v0 > best[s0]) { best[s0] = v0; bcol[s0] = c01; }
                if (v1 > best[s0]) { best[s0] = v1; bcol[s0] = c01 + 1; }
                if (v2 > best[s1]) { best[s1] = v2; bcol[s1] = c01; }
                if (v3 > best[s1]) { best[s1] = v3; bcol[s1] = c01 + 1; }
            }
        }
        __syncthreads();
        if (t + 2 < NTILES) load_b_tile(smem_base, t + 2, tid);
        CP_COMMIT();
    }

    // ---- quad reduce ----
#pragma unroll
    for (int s = 0; s < 4; s++) {
        float v = best[s];
        int c = bcol[s];
#pragma unroll
        for (int off = 1; off <= 2; off <<= 1) {
            float ov = __shfl_xor_sync(0xffffffffu, v, off);
            int oc = __shfl_xor_sync(0xffffffffu, c, off);
            if (ov > v || (ov == v && oc < c)) { v = ov; c = oc; }
        }
        if ((lane & 3) == 0) {
            int rowl = wr * 32 + (s >> 1) * 16 + (s & 1) * 8 + g;
            RED[wc * 128 + rowl] = make_float2(v, __int_as_float(c));
        }
    }
    __syncthreads();

    // ---- exact fp32 rescore of the two half-winners per row ----
    if (tid < 128) {
        int row = tid, rg = row0 + row;
        float xv[64];
        const float4* ip = (const float4*)(input + (size_t)rg * 64);
        const float4* pp = (const float4*)(g_pe + (size_t)(rg & 1023) * 64);
#pragma unroll
        for (int q = 0; q < 16; q++) {
            float4 a = ip[q], b = pp[q];
            xv[q * 4 + 0] = a.x + b.x; xv[q * 4 + 1] = a.y + b.y;
            xv[q * 4 + 2] = a.z + b.z; xv[q * 4 + 3] = a.w + b.w;
        }
        int c0 = __float_as_int(RED[row].y);
        int c1 = __float_as_int(RED[128 + row].y);
        float s0 = g_cn[c0], s1 = g_cn[c1];
        const float4* e0 = (const float4*)(g_et + (size_t)c0 * 64);
        const float4* e1 = (const float4*)(g_et + (size_t)c1 * 64);
#pragma unroll
        for (int q = 0; q < 16; q++) {
            float4 ea = e0[q], eb = e1[q];
            s0 = fmaf(xv[q * 4 + 0], ea.x, s0); s0 = fmaf(xv[q * 4 + 1], ea.y, s0);
            s0 = fmaf(xv[q * 4 + 2], ea.z, s0); s0 = fmaf(xv[q * 4 + 3], ea.w, s0);
            s1 = fmaf(xv[q * 4 + 0], eb.x, s1); s1 = fmaf(xv[q * 4 + 1], eb.y, s1);
            s1 = fmaf(xv[q * 4 + 2], eb.z, s1); s1 = fmaf(xv[q * 4 + 3], eb.w, s1);
        }
        int bj = (s1 > s0 || (s1 == s0 && c1 < c0)) ? c1 : c0;
        IndSh[row] = bj;
        if (full) out[OFF_IND + rg] = (float)bj;
        atomicAdd(&g_counts[bj], 1.0f);
    }
    __syncthreads();

    // ---- epilogue: quantize gather, loss, embed_sum scatter ----
    {
        float lsum = 0.0f;
        for (int it = 0; it < 16; it++) {
            int rloc = wid * 16 + it;
            int rg = row0 + rloc;
            int j = IndSh[rloc];
#pragma unroll
            for (int h2 = 0; h2 < 2; h2++) {
                int k = lane + 32 * h2;
                float ev = g_et[(size_t)j * 64 + k];
                float iv = input[(size_t)rg * 64 + k];
                float dd = ev - iv;
                lsum += dd * dd;
                out[OFF_Q + (size_t)rg * 64 + k] = ev;
                float xv2 = iv + g_pe[(rg & 1023) * 64 + k];
                atomicAdd(&g_esum[(size_t)k * NCODES + j], xv2);
            }
        }
#pragma unroll
        for (int off = 16; off; off >>= 1)
            lsum += __shfl_down_sync(0xffffffffu, lsum, off);
        if (lane == 0) atomicAdd(smf + W_LOSS, lsum);
    }
    __syncthreads();
    if (tid == 0) atomicAdd(&g_loss, smf[W_LOSS]);
}

// ---------------------------------------------------------------------------
// fused finalize: new_cluster, new_embed_avg, new_embed, loss.
// grid 512 x 256 (float4 loads; scalar stores — out offsets are odd).
// ---------------------------------------------------------------------------
__global__ void vq_fin(const float* __restrict__ cs,
                       const float* __restrict__ ea,
                       float* __restrict__ out) {
    int i4 = blockIdx.x * 256 + threadIdx.x;    // 0..131071
    int idx = i4 * 4;
    float4 e4 = ((const float4*)ea)[i4];
    float4 s4 = ((const float4*)g_esum)[i4];
    float nea0 = 0.8f * e4.x + 0.2f * s4.x;
    float nea1 = 0.8f * e4.y + 0.2f * s4.y;
    float nea2 = 0.8f * e4.z + 0.2f * s4.z;
    float nea3 = 0.8f * e4.w + 0.2f * s4.w;
    out[OFF_EA + idx + 0] = nea0;
    out[OFF_EA + idx + 1] = nea1;
    out[OFF_EA + idx + 2] = nea2;
    out[OFF_EA + idx + 3] = nea3;

    int jb = (idx & (NCODES - 1)) >> 2;
    float4 c4 = ((const float4*)cs)[jb];
    float4 t4 = ((const float4*)g_counts)[jb];
    float nc0 = 0.8f * c4.x + 0.2f * t4.x;
    float nc1 = 0.8f * c4.y + 0.2f * t4.y;
    float nc2 = 0.8f * c4.z + 0.2f * t4.z;
    float nc3 = 0.8f * c4.w + 0.2f * t4.w;

    float total = g_total;
    float denom = total + NCODES * 1e-5f;
    float sc = total / denom;
    out[OFF_NE + idx + 0] = nea0 / ((nc0 + 1e-5f) * sc);
    out[OFF_NE + idx + 1] = nea1 / ((nc1 + 1e-5f) * sc);
    out[OFF_NE + idx + 2] = nea2 / ((nc2 + 1e-5f) * sc);
    out[OFF_NE + idx + 3] = nea3 / ((nc3 + 1e-5f) * sc);

    if (idx < NCODES) {
        out[OFF_NC + idx + 0] = nc0;
        out[OFF_NC + idx + 1] = nc1;
        out[OFF_NC + idx + 2] = nc2;
        out[OFF_NC + idx + 3] = nc3;
    }
    if (i4 == 0) out[OFF_LOSS] = g_loss * (1.0f / 2097152.0f);
}

// ---------------------------------------------------------------------------
extern "C" void kernel_launch(void* const* d_in, const int* in_sizes, int n_in,
                              void* d_out, int out_size) {
    const float* input = (const float*)d_in[0];
    const float* embed = (const float*)d_in[1];
    const float* pos   = (const float*)d_in[2];
    const float* cs    = (const float*)d_in[3];
    const float* ea    = (const float*)d_in[4];
    float* out = (float*)d_out;

    cudaFuncSetAttribute(vq_main, cudaFuncAttributeMaxDynamicSharedMemorySize,
                         SMEM_TOTAL);
    int full = (out_size >= OUT_FULL) ? 1 : 0;

    vq_prep0<<<512, 256>>>(pos, cs);
    vq_prep1<<<256, 256>>>(embed);
    vq_main<<<256, 256, SMEM_TOTAL>>>(input, out, full);
    if (full) vq_fin<<<512, 256>>>(cs, ea, out);
}

// round 14
// speedup vs baseline: 1.0358x; 1.0060x over previous
#include <cuda_runtime.h>
#include <cuda_fp16.h>
#include <cstdint>

// ---------------------------------------------------------------------------
// VectorQuantize via mma.sync.m16n8k16.f16 (3xFP16 emulated fp32) + exact
// fp32 rescore. vq_main = R4 champion GEMM loop; float2 epilogue; fin with
// 2 units/thread. Analytic total; float4 prep.
// ---------------------------------------------------------------------------

#define NCODES 8192
#define OFF_Q     0
#define OFF_IND   2097152
#define OFF_LOSS  2129920
#define OFF_NC    2129921
#define OFF_EA    2138113
#define OFF_NE    2662401
#define OUT_FULL  3186689

#define RPB    128
#define NTILES 64

// smem word offsets
#define W_AH   0        // [4 kc16][128 row][8 w] fp16x2 words
#define W_AL   4096
#define W_B    8192     // 2 stages x (hi 4096 + lo 4096)
#define W_CN   24576    // 2 x 128
#define W_IND  24832
#define W_RED  24960    // 2 halves x 128 float2
#define W_LOSS 25472
#define SMEM_TOTAL 101920

// device scratch
__device__ __align__(16) float g_pe[65536];
__device__ __align__(16) float g_cn[NCODES];
__device__ __align__(16) float g_counts[NCODES];
__device__ __align__(16) float g_esum[64 * NCODES];
__device__ __align__(16) float g_et[NCODES * 64];       // E^T fp32 [j][k]
__device__ __align__(16) uint32_t g_eh16[NCODES * 32];  // E^T fp16x2 hi [j][k/2]
__device__ __align__(16) uint32_t g_el16[NCODES * 32];  // E^T fp16x2 lo
__device__ float g_loss, g_total;

// ---------------------------------------------------------------------------
__device__ __forceinline__ uint32_t smem_u32(const void* p) {
    uint32_t a;
    asm("{ .reg .u64 t; cvta.to.shared.u64 t, %1; cvt.u32.u64 %0, t; }"
        : "=r"(a) : "l"(p));
    return a;
}
__device__ __forceinline__ void mma16(float* d, const uint32_t* a,
                                      uint32_t b0, uint32_t b1) {
    asm volatile(
        "mma.sync.aligned.m16n8k16.row.col.f32.f16.f16.f32 "
        "{%0,%1,%2,%3}, {%4,%5,%6,%7}, {%8,%9}, {%0,%1,%2,%3};"
        : "+f"(d[0]), "+f"(d[1]), "+f"(d[2]), "+f"(d[3])
        : "r"(a[0]), "r"(a[1]), "r"(a[2]), "r"(a[3]), "r"(b0), "r"(b1));
}
__device__ __forceinline__ void cp16(uint32_t dst, const void* src) {
    asm volatile("cp.async.cg.shared.global [%0], [%1], 16;"
                 :: "r"(dst), "l"(src) : "memory");
}
#define CP_COMMIT() asm volatile("cp.async.commit_group;" ::: "memory")
#define CP_WAIT1()  asm volatile("cp.async.wait_group 1;" ::: "memory")

__device__ __forceinline__ uint32_t pkh(float a, float b) {
    __half2 h = __floats2half2_rn(a, b);
    return *(uint32_t*)&h;
}

// ---------------------------------------------------------------------------
// prep0: float4 zero g_esum/g_counts, float4 PE build, cs-sum -> g_total.
// grid 512 x 256.
// ---------------------------------------------------------------------------
__global__ void vq_prep0(const float* __restrict__ pos_emb,
                         const float* __restrict__ cs) {
    const int tid = threadIdx.x;
    int i4 = blockIdx.x * 256 + tid;            // 0..131071 float4 units
    float4 z = make_float4(0.f, 0.f, 0.f, 0.f);
    ((float4*)g_esum)[i4] = z;
    if (i4 < 16384) {
        int idx = i4 * 4;
        int j = idx & 63, i = (idx >> 6) & 63, c = idx >> 12;
        int s = ((i >> 2) << 4) + (j >> 2);
        int d = (c << 4) + ((i & 3) << 2);      // (j&3)==0
        ((float4*)g_pe)[i4] = *(const float4*)(pos_emb + s * 256 + d);
    }
    if (i4 < 2048) ((float4*)g_counts)[i4] = z;

    if (blockIdx.x == 0) {
        float ssum = 0.0f;
#pragma unroll
        for (int q = 0; q < 8; q++) {
            float4 v = ((const float4*)cs)[tid + q * 256];
            ssum += v.x + v.y + v.z + v.w;
        }
        __shared__ float sh[256];
        sh[tid] = ssum;
        __syncthreads();
        for (int s = 128; s; s >>= 1) {
            if (tid < s) sh[tid] += sh[tid + s];
            __syncthreads();
        }
        if (tid == 0) {
            g_total = 0.8f * sh[0] + 0.2f * 32768.0f;
            g_loss = 0.0f;
        }
    }
}

// ---------------------------------------------------------------------------
// prep1: transpose embed -> g_et, fp16 hi/lo splits, code norms.
// grid 256 x 256 (block = 32 codes).
// ---------------------------------------------------------------------------
__global__ void vq_prep1(const float* __restrict__ embed) {
    __shared__ float sE[64][33];
    __shared__ float scn[32][8];
    const int tid = threadIdx.x;
    const int j0 = blockIdx.x * 32;
#pragma unroll
    for (int pass = 0; pass < 8; pass++) {
        int k = pass * 8 + (tid >> 5);
        int jl = tid & 31;
        sE[k][jl] = embed[(size_t)k * NCODES + j0 + jl];
    }
    __syncthreads();
    const int jl = tid & 31, p = tid >> 5;
    const int j = j0 + jl;
    float ssum = 0.0f;
#pragma unroll
    for (int w = 0; w < 4; w++) {
        int k = p * 8 + 2 * w;
        float v0 = sE[k][jl], v1 = sE[k + 1][jl];
        ssum += v0 * v0 + v1 * v1;
        *(float2*)(g_et + (size_t)j * 64 + k) = make_float2(v0, v1);
        __half h0 = __float2half_rn(v0), h1 = __float2half_rn(v1);
        float l0 = v0 - __half2float(h0), l1 = v1 - __half2float(h1);
        g_eh16[(size_t)j * 32 + (k >> 1)] =
            pkh(__half2float(h0), __half2float(h1));
        g_el16[(size_t)j * 32 + (k >> 1)] = pkh(l0, l1);
    }
    scn[jl][p] = ssum;
    __syncthreads();
    if (tid < 32) {
        float s = 0.0f;
#pragma unroll
        for (int q = 0; q < 8; q++) s += scn[tid][q];
        g_cn[j0 + tid] = -0.5f * s;
    }
}

// ---------------------------------------------------------------------------
// async B tile: g_eh16/g_el16 [j][k/2] -> smem [kc16][col][w] swizzled
// ---------------------------------------------------------------------------
__device__ __forceinline__ void load_b_tile(uint32_t smem_base, int t, int tid) {
    const int cb = t * 128;
    const uint32_t bb = smem_base + (uint32_t)(W_B + (t & 1) * 8192) * 4u;
#pragma unroll
    for (int i = 0; i < 8; i++) {
        int c = tid + (i << 8);             // 0..2047
        int arr = c >> 10;                  // 0 hi, 1 lo
        int rem = c & 1023;
        int j = rem >> 3, ch = rem & 7;     // ch: 16B chunk within 128B row
        int kc16 = ch >> 1, half8 = ch & 1;
        const uint32_t* src = (arr ? g_el16 : g_eh16) + (size_t)(cb + j) * 32 + ch * 4;
        uint32_t dstw = (uint32_t)(arr * 4096 + kc16 * 1024 + j * 8 +
                                   ((half8 ^ ((j >> 2) & 1)) << 2));
        cp16(bb + dstw * 4u, src);
    }
    if (tid < 32)
        cp16(smem_base + (uint32_t)(W_CN + (t & 1) * 128) * 4u + tid * 16,
             g_cn + cb + tid * 4);
}

// ---------------------------------------------------------------------------
// main: 256 CTAs x 256 threads, 2 CTAs/SM. warp tile 32x64, 3xFP16 mma.
// (R4 champion GEMM loop; float2-vectorized epilogue)
// ---------------------------------------------------------------------------
__global__ void __launch_bounds__(256, 2)
vq_main(const float* __restrict__ input, float* __restrict__ out, int full) {
    extern __shared__ float smf[];
    const uint32_t smem_base = smem_u32(smf);
    const int tid = threadIdx.x, wid = tid >> 5, lane = tid & 31;
    const int wr = wid >> 1, wc = wid & 1;
    const int g = lane >> 2, kl = lane & 3;
    const int row0 = blockIdx.x * RPB;

    int* IndSh = (int*)(smf + W_IND);
    float2* RED = (float2*)(smf + W_RED);
    if (tid == 0) smf[W_LOSS] = 0.0f;

    // ---- A build: X = input + pe, fp16 hi/lo, fragment-native layout ----
    {
        int row = tid >> 1, h = tid & 1, rg = row0 + row;
        const float4* ip = (const float4*)(input + (size_t)rg * 64);
        const float4* pp = (const float4*)(g_pe + (size_t)(rg & 1023) * 64);
        int swz = ((row >> 2) & 1) << 2;
#pragma unroll
        for (int i = 0; i < 8; i++) {
            int q = h * 8 + i;
            int k0 = 4 * q, kc16 = k0 >> 4, o = k0 & 15, w = o >> 1;
            float4 a = ip[q], b = pp[q];
            float x0 = a.x + b.x, x1 = a.y + b.y;
            float x2 = a.z + b.z, x3 = a.w + b.w;
            __half h0 = __float2half_rn(x0), h1 = __float2half_rn(x1);
            __half h2 = __float2half_rn(x2), h3 = __float2half_rn(x3);
            float l0 = x0 - __half2float(h0), l1 = x1 - __half2float(h1);
            float l2 = x2 - __half2float(h2), l3 = x3 - __half2float(h3);
            int wsw = w ^ swz;
            int off = kc16 * 1024 + row * 8 + wsw;
            *(uint2*)(smf + W_AH + off) =
                make_uint2(pkh(__half2float(h0), __half2float(h1)),
                           pkh(__half2float(h2), __half2float(h3)));
            *(uint2*)(smf + W_AL + off) = make_uint2(pkh(l0, l1), pkh(l2, l3));
        }
    }
    load_b_tile(smem_base, 0, tid); CP_COMMIT();
    load_b_tile(smem_base, 1, tid); CP_COMMIT();

    float best[4];
    int bcol[4];
#pragma unroll
    for (int s = 0; s < 4; s++) { best[s] = -3.4e38f; bcol[s] = 0; }

    const uint32_t* AH = (const uint32_t*)(smf + W_AH);
    const uint32_t* ALp = (const uint32_t*)(smf + W_AL);
    const int aswz = ((g >> 2) & 1) << 2;
    const int w0 = kl ^ aswz, w1 = (kl + 4) ^ aswz;

    for (int t = 0; t < NTILES; t++) {
        CP_WAIT1();
        __syncthreads();
        const uint32_t* BH = (const uint32_t*)(smf + W_B + (t & 1) * 8192);
        const uint32_t* BL = BH + 4096;
        const float* cn = smf + W_CN + (t & 1) * 128 + wc * 64;

        float acc[2][8][4];
#pragma unroll
        for (int nf = 0; nf < 8; nf++) {
            float c0 = cn[nf * 8 + 2 * kl];
            float c1 = cn[nf * 8 + 2 * kl + 1];
#pragma unroll
            for (int m = 0; m < 2; m++) {
                acc[m][nf][0] = c0; acc[m][nf][1] = c1;
                acc[m][nf][2] = c0; acc[m][nf][3] = c1;
            }
        }
#pragma unroll
        for (int kc16 = 0; kc16 < 4; kc16++) {
            uint32_t ah[2][4], al[2][4];
#pragma unroll
            for (int m = 0; m < 2; m++) {
                int base = kc16 * 1024 + (wr * 32 + m * 16 + g) * 8;
                ah[m][0] = AH[base + w0];      ah[m][1] = AH[base + 64 + w0];
                ah[m][2] = AH[base + w1];      ah[m][3] = AH[base + 64 + w1];
                al[m][0] = ALp[base + w0];     al[m][1] = ALp[base + 64 + w0];
                al[m][2] = ALp[base + w1];     al[m][3] = ALp[base + 64 + w1];
            }
#pragma unroll
            for (int nf = 0; nf < 8; nf++) {
                int bb = kc16 * 1024 + (wc * 64 + nf * 8 + g) * 8;
                uint32_t bh0 = BH[bb + w0], bh1 = BH[bb + w1];
                uint32_t bl0 = BL[bb + w0], bl1 = BL[bb + w1];
#pragma unroll
                for (int m = 0; m < 2; m++) {
                    mma16(acc[m][nf], ah[m], bh0, bh1);
                    mma16(acc[m][nf], ah[m], bl0, bl1);
                    mma16(acc[m][nf], al[m], bh0, bh1);
                }
            }
        }
        // running per-slot argmax (ascending cols -> strict > keeps low index)
        int colbase0 = t * 128 + wc * 64 + 2 * kl;
#pragma unroll
        for (int m = 0; m < 2; m++) {
#pragma unroll
            for (int nf = 0; nf < 8; nf++) {
                int c01 = colbase0 + nf * 8;
                float v0 = acc[m][nf][0], v1 = acc[m][nf][1];
                float v2 = acc[m][nf][2], v3 = acc[m][nf][3];
                int s0 = 2 * m, s1 = 2 * m + 1;
                if (v0 > best[s0]) { best[s0] = v0; bcol[s0] = c01; }
                if (v1 > best[s0]) { best[s0] = v1; bcol[s0] = c01 + 1; }
                if (v2 > best[s1]) { best[s1] = v2; bcol[s1] = c01; }
                if (v3 > best[s1]) { best[s1] = v3; bcol[s1] = c01 + 1; }
            }
        }
        __syncthreads();
        if (t + 2 < NTILES) load_b_tile(smem_base, t + 2, tid);
        CP_COMMIT();
    }

    // ---- quad reduce ----
#pragma unroll
    for (int s = 0; s < 4; s++) {
        float v = best[s];
        int c = bcol[s];
#pragma unroll
        for (int off = 1; off <= 2; off <<= 1) {
            float ov = __shfl_xor_sync(0xffffffffu, v, off);
            int oc = __shfl_xor_sync(0xffffffffu, c, off);
            if (ov > v || (ov == v && oc < c)) { v = ov; c = oc; }
        }
        if ((lane & 3) == 0) {
            int rowl = wr * 32 + (s >> 1) * 16 + (s & 1) * 8 + g;
            RED[wc * 128 + rowl] = make_float2(v, __int_as_float(c));
        }
    }
    __syncthreads();

    // ---- exact fp32 rescore of the two half-winners per row ----
    if (tid < 128) {
        int row = tid, rg = row0 + row;
        float xv[64];
        const float4* ip = (const float4*)(input + (size_t)rg * 64);
        const float4* pp = (const float4*)(g_pe + (size_t)(rg & 1023) * 64);
#pragma unroll
        for (int q = 0; q < 16; q++) {
            float4 a = ip[q], b = pp[q];
            xv[q * 4 + 0] = a.x + b.x; xv[q * 4 + 1] = a.y + b.y;
            xv[q * 4 + 2] = a.z + b.z; xv[q * 4 + 3] = a.w + b.w;
        }
        int c0 = __float_as_int(RED[row].y);
        int c1 = __float_as_int(RED[128 + row].y);
        float s0 = g_cn[c0], s1 = g_cn[c1];
        const float4* e0 = (const float4*)(g_et + (size_t)c0 * 64);
        const float4* e1 = (const float4*)(g_et + (size_t)c1 * 64);
#pragma unroll
        for (int q = 0; q < 16; q++) {
            float4 ea = e0[q], eb = e1[q];
            s0 = fmaf(xv[q * 4 + 0], ea.x, s0); s0 = fmaf(xv[q * 4 + 1], ea.y, s0);
            s0 = fmaf(xv[q * 4 + 2], ea.z, s0); s0 = fmaf(xv[q * 4 + 3], ea.w, s0);
            s1 = fmaf(xv[q * 4 + 0], eb.x, s1); s1 = fmaf(xv[q * 4 + 1], eb.y, s1);
            s1 = fmaf(xv[q * 4 + 2], eb.z, s1); s1 = fmaf(xv[q * 4 + 3], eb.w, s1);
        }
        int bj = (s1 > s0 || (s1 == s0 && c1 < c0)) ? c1 : c0;
        IndSh[row] = bj;
        if (full) out[OFF_IND + rg] = (float)bj;
        atomicAdd(&g_counts[bj], 1.0f);
    }
    __syncthreads();

    // ---- epilogue: quantize gather, loss, embed_sum scatter (float2) ----
    {
        float lsum = 0.0f;
        const int k0 = 2 * lane;
        for (int it = 0; it < 16; it++) {
            int rloc = wid * 16 + it;
            int rg = row0 + rloc;
            int j = IndSh[rloc];
            float2 ev = *(const float2*)(g_et + (size_t)j * 64 + k0);
            float2 iv = *(const float2*)(input + (size_t)rg * 64 + k0);
            float2 pe = *(const float2*)(g_pe + (size_t)(rg & 1023) * 64 + k0);
            float d0 = ev.x - iv.x, d1 = ev.y - iv.y;
            lsum += d0 * d0 + d1 * d1;
            *(float2*)(out + OFF_Q + (size_t)rg * 64 + k0) = ev;
            atomicAdd(&g_esum[(size_t)k0 * NCODES + j], iv.x + pe.x);
            atomicAdd(&g_esum[(size_t)(k0 + 1) * NCODES + j], iv.y + pe.y);
        }
#pragma unroll
        for (int off = 16; off; off >>= 1)
            lsum += __shfl_down_sync(0xffffffffu, lsum, off);
        if (lane == 0) atomicAdd(smf + W_LOSS, lsum);
    }
    __syncthreads();
    if (tid == 0) atomicAdd(&g_loss, smf[W_LOSS]);
}

// ---------------------------------------------------------------------------
// fused finalize: new_cluster, new_embed_avg, new_embed, loss.
// grid 256 x 256, 2 float4 units per thread (float4 loads; scalar stores).
// ---------------------------------------------------------------------------
__global__ void vq_fin(const float* __restrict__ cs,
                       const float* __restrict__ ea,
                       float* __restrict__ out) {
    const int base4 = blockIdx.x * 512 + threadIdx.x;
    float total = g_total;
    float denom = total + NCODES * 1e-5f;
    float sc = total / denom;
#pragma unroll
    for (int u = 0; u < 2; u++) {
        int i4 = base4 + u * 256;               // 0..131071
        int idx = i4 * 4;
        float4 e4 = ((const float4*)ea)[i4];
        float4 s4 = ((const float4*)g_esum)[i4];
        float nea0 = 0.8f * e4.x + 0.2f * s4.x;
        float nea1 = 0.8f * e4.y + 0.2f * s4.y;
        float nea2 = 0.8f * e4.z + 0.2f * s4.z;
        float nea3 = 0.8f * e4.w + 0.2f * s4.w;
        out[OFF_EA + idx + 0] = nea0;
        out[OFF_EA + idx + 1] = nea1;
        out[OFF_EA + idx + 2] = nea2;
        out[OFF_EA + idx + 3] = nea3;

        int jb = (idx & (NCODES - 1)) >> 2;
        float4 c4 = ((const float4*)cs)[jb];
        float4 t4 = ((const float4*)g_counts)[jb];
        float nc0 = 0.8f * c4.x + 0.2f * t4.x;
        float nc1 = 0.8f * c4.y + 0.2f * t4.y;
        float nc2 = 0.8f * c4.z + 0.2f * t4.z;
        float nc3 = 0.8f * c4.w + 0.2f * t4.w;

        out[OFF_NE + idx + 0] = nea0 / ((nc0 + 1e-5f) * sc);
        out[OFF_NE + idx + 1] = nea1 / ((nc1 + 1e-5f) * sc);
        out[OFF_NE + idx + 2] = nea2 / ((nc2 + 1e-5f) * sc);
        out[OFF_NE + idx + 3] = nea3 / ((nc3 + 1e-5f) * sc);

        if (idx < NCODES) {
            out[OFF_NC + idx + 0] = nc0;
            out[OFF_NC + idx + 1] = nc1;
            out[OFF_NC + idx + 2] = nc2;
            out[OFF_NC + idx + 3] = nc3;
        }
        if (i4 == 0) out[OFF_LOSS] = g_loss * (1.0f / 2097152.0f);
    }
}

// ---------------------------------------------------------------------------
extern "C" void kernel_launch(void* const* d_in, const int* in_sizes, int n_in,
                              void* d_out, int out_size) {
    const float* input = (const float*)d_in[0];
    const float* embed = (const float*)d_in[1];
    const float* pos   = (const float*)d_in[2];
    const float* cs    = (const float*)d_in[3];
    const float* ea    = (const float*)d_in[4];
    float* out = (float*)d_out;

    cudaFuncSetAttribute(vq_main, cudaFuncAttributeMaxDynamicSharedMemorySize,
                         SMEM_TOTAL);
    int full = (out_size >= OUT_FULL) ? 1 : 0;

    vq_prep0<<<512, 256>>>(pos, cs);
    vq_prep1<<<256, 256>>>(embed);
    vq_main<<<256, 256, SMEM_TOTAL>>>(input, out, full);
    if (full) vq_fin<<<256, 256>>>(cs, ea, out);
}

// round 15
// speedup vs baseline: 1.0383x; 1.0024x over previous
#include <cuda_runtime.h>
#include <cuda_fp16.h>
#include <cstdint>

// ---------------------------------------------------------------------------
// VectorQuantize via mma.sync.m16n8k16.f16 (3xFP16 emulated fp32) + exact
// fp32 rescore. vq_main = R4 champion GEMM loop + float2 epilogue (R14).
// vq_fin = R13 grid-512 variant (measured 6.14us). Analytic total; float4
// prep.
// ---------------------------------------------------------------------------

#define NCODES 8192
#define OFF_Q     0
#define OFF_IND   2097152
#define OFF_LOSS  2129920
#define OFF_NC    2129921
#define OFF_EA    2138113
#define OFF_NE    2662401
#define OUT_FULL  3186689

#define RPB    128
#define NTILES 64

// smem word offsets
#define W_AH   0        // [4 kc16][128 row][8 w] fp16x2 words
#define W_AL   4096
#define W_B    8192     // 2 stages x (hi 4096 + lo 4096)
#define W_CN   24576    // 2 x 128
#define W_IND  24832
#define W_RED  24960    // 2 halves x 128 float2
#define W_LOSS 25472
#define SMEM_TOTAL 101920

// device scratch
__device__ __align__(16) float g_pe[65536];
__device__ __align__(16) float g_cn[NCODES];
__device__ __align__(16) float g_counts[NCODES];
__device__ __align__(16) float g_esum[64 * NCODES];
__device__ __align__(16) float g_et[NCODES * 64];       // E^T fp32 [j][k]
__device__ __align__(16) uint32_t g_eh16[NCODES * 32];  // E^T fp16x2 hi [j][k/2]
__device__ __align__(16) uint32_t g_el16[NCODES * 32];  // E^T fp16x2 lo
__device__ float g_loss, g_total;

// ---------------------------------------------------------------------------
__device__ __forceinline__ uint32_t smem_u32(const void* p) {
    uint32_t a;
    asm("{ .reg .u64 t; cvta.to.shared.u64 t, %1; cvt.u32.u64 %0, t; }"
        : "=r"(a) : "l"(p));
    return a;
}
__device__ __forceinline__ void mma16(float* d, const uint32_t* a,
                                      uint32_t b0, uint32_t b1) {
    asm volatile(
        "mma.sync.aligned.m16n8k16.row.col.f32.f16.f16.f32 "
        "{%0,%1,%2,%3}, {%4,%5,%6,%7}, {%8,%9}, {%0,%1,%2,%3};"
        : "+f"(d[0]), "+f"(d[1]), "+f"(d[2]), "+f"(d[3])
        : "r"(a[0]), "r"(a[1]), "r"(a[2]), "r"(a[3]), "r"(b0), "r"(b1));
}
__device__ __forceinline__ void cp16(uint32_t dst, const void* src) {
    asm volatile("cp.async.cg.shared.global [%0], [%1], 16;"
                 :: "r"(dst), "l"(src) : "memory");
}
#define CP_COMMIT() asm volatile("cp.async.commit_group;" ::: "memory")
#define CP_WAIT1()  asm volatile("cp.async.wait_group 1;" ::: "memory")

__device__ __forceinline__ uint32_t pkh(float a, float b) {
    __half2 h = __floats2half2_rn(a, b);
    return *(uint32_t*)&h;
}

// ---------------------------------------------------------------------------
// prep0: float4 zero g_esum/g_counts, float4 PE build, cs-sum -> g_total.
// grid 512 x 256.
// ---------------------------------------------------------------------------
__global__ void vq_prep0(const float* __restrict__ pos_emb,
                         const float* __restrict__ cs) {
    const int tid = threadIdx.x;
    int i4 = blockIdx.x * 256 + tid;            // 0..131071 float4 units
    float4 z = make_float4(0.f, 0.f, 0.f, 0.f);
    ((float4*)g_esum)[i4] = z;
    if (i4 < 16384) {
        int idx = i4 * 4;
        int j = idx & 63, i = (idx >> 6) & 63, c = idx >> 12;
        int s = ((i >> 2) << 4) + (j >> 2);
        int d = (c << 4) + ((i & 3) << 2);      // (j&3)==0
        ((float4*)g_pe)[i4] = *(const float4*)(pos_emb + s * 256 + d);
    }
    if (i4 < 2048) ((float4*)g_counts)[i4] = z;

    if (blockIdx.x == 0) {
        float ssum = 0.0f;
#pragma unroll
        for (int q = 0; q < 8; q++) {
            float4 v = ((const float4*)cs)[tid + q * 256];
            ssum += v.x + v.y + v.z + v.w;
        }
        __shared__ float sh[256];
        sh[tid] = ssum;
        __syncthreads();
        for (int s = 128; s; s >>= 1) {
            if (tid < s) sh[tid] += sh[tid + s];
            __syncthreads();
        }
        if (tid == 0) {
            g_total = 0.8f * sh[0] + 0.2f * 32768.0f;
            g_loss = 0.0f;
        }
    }
}

// ---------------------------------------------------------------------------
// prep1: transpose embed -> g_et, fp16 hi/lo splits, code norms.
// grid 256 x 256 (block = 32 codes).
// ---------------------------------------------------------------------------
__global__ void vq_prep1(const float* __restrict__ embed) {
    __shared__ float sE[64][33];
    __shared__ float scn[32][8];
    const int tid = threadIdx.x;
    const int j0 = blockIdx.x * 32;
#pragma unroll
    for (int pass = 0; pass < 8; pass++) {
        int k = pass * 8 + (tid >> 5);
        int jl = tid & 31;
        sE[k][jl] = embed[(size_t)k * NCODES + j0 + jl];
    }
    __syncthreads();
    const int jl = tid & 31, p = tid >> 5;
    const int j = j0 + jl;
    float ssum = 0.0f;
#pragma unroll
    for (int w = 0; w < 4; w++) {
        int k = p * 8 + 2 * w;
        float v0 = sE[k][jl], v1 = sE[k + 1][jl];
        ssum += v0 * v0 + v1 * v1;
        *(float2*)(g_et + (size_t)j * 64 + k) = make_float2(v0, v1);
        __half h0 = __float2half_rn(v0), h1 = __float2half_rn(v1);
        float l0 = v0 - __half2float(h0), l1 = v1 - __half2float(h1);
        g_eh16[(size_t)j * 32 + (k >> 1)] =
            pkh(__half2float(h0), __half2float(h1));
        g_el16[(size_t)j * 32 + (k >> 1)] = pkh(l0, l1);
    }
    scn[jl][p] = ssum;
    __syncthreads();
    if (tid < 32) {
        float s = 0.0f;
#pragma unroll
        for (int q = 0; q < 8; q++) s += scn[tid][q];
        g_cn[j0 + tid] = -0.5f * s;
    }
}

// ---------------------------------------------------------------------------
// async B tile: g_eh16/g_el16 [j][k/2] -> smem [kc16][col][w] swizzled
// ---------------------------------------------------------------------------
__device__ __forceinline__ void load_b_tile(uint32_t smem_base, int t, int tid) {
    const int cb = t * 128;
    const uint32_t bb = smem_base + (uint32_t)(W_B + (t & 1) * 8192) * 4u;
#pragma unroll
    for (int i = 0; i < 8; i++) {
        int c = tid + (i << 8);             // 0..2047
        int arr = c >> 10;                  // 0 hi, 1 lo
        int rem = c & 1023;
        int j = rem >> 3, ch = rem & 7;     // ch: 16B chunk within 128B row
        int kc16 = ch >> 1, half8 = ch & 1;
        const uint32_t* src = (arr ? g_el16 : g_eh16) + (size_t)(cb + j) * 32 + ch * 4;
        uint32_t dstw = (uint32_t)(arr * 4096 + kc16 * 1024 + j * 8 +
                                   ((half8 ^ ((j >> 2) & 1)) << 2));
        cp16(bb + dstw * 4u, src);
    }
    if (tid < 32)
        cp16(smem_base + (uint32_t)(W_CN + (t & 1) * 128) * 4u + tid * 16,
             g_cn + cb + tid * 4);
}

// ---------------------------------------------------------------------------
// main: 256 CTAs x 256 threads, 2 CTAs/SM. warp tile 32x64, 3xFP16 mma.
// (R4 champion GEMM loop; float2-vectorized epilogue)
// ---------------------------------------------------------------------------
__global__ void __launch_bounds__(256, 2)
vq_main(const float* __restrict__ input, float* __restrict__ out, int full) {
    extern __shared__ float smf[];
    const uint32_t smem_base = smem_u32(smf);
    const int tid = threadIdx.x, wid = tid >> 5, lane = tid & 31;
    const int wr = wid >> 1, wc = wid & 1;
    const int g = lane >> 2, kl = lane & 3;
    const int row0 = blockIdx.x * RPB;

    int* IndSh = (int*)(smf + W_IND);
    float2* RED = (float2*)(smf + W_RED);
    if (tid == 0) smf[W_LOSS] = 0.0f;

    // ---- A build: X = input + pe, fp16 hi/lo, fragment-native layout ----
    {
        int row = tid >> 1, h = tid & 1, rg = row0 + row;
        const float4* ip = (const float4*)(input + (size_t)rg * 64);
        const float4* pp = (const float4*)(g_pe + (size_t)(rg & 1023) * 64);
        int swz = ((row >> 2) & 1) << 2;
#pragma unroll
        for (int i = 0; i < 8; i++) {
            int q = h * 8 + i;
            int k0 = 4 * q, kc16 = k0 >> 4, o = k0 & 15, w = o >> 1;
            float4 a = ip[q], b = pp[q];
            float x0 = a.x + b.x, x1 = a.y + b.y;
            float x2 = a.z + b.z, x3 = a.w + b.w;
            __half h0 = __float2half_rn(x0), h1 = __float2half_rn(x1);
            __half h2 = __float2half_rn(x2), h3 = __float2half_rn(x3);
            float l0 = x0 - __half2float(h0), l1 = x1 - __half2float(h1);
            float l2 = x2 - __half2float(h2), l3 = x3 - __half2float(h3);
            int wsw = w ^ swz;
            int off = kc16 * 1024 + row * 8 + wsw;
            *(uint2*)(smf + W_AH + off) =
                make_uint2(pkh(__half2float(h0), __half2float(h1)),
                           pkh(__half2float(h2), __half2float(h3)));
            *(uint2*)(smf + W_AL + off) = make_uint2(pkh(l0, l1), pkh(l2, l3));
        }
    }
    load_b_tile(smem_base, 0, tid); CP_COMMIT();
    load_b_tile(smem_base, 1, tid); CP_COMMIT();

    float best[4];
    int bcol[4];
#pragma unroll
    for (int s = 0; s < 4; s++) { best[s] = -3.4e38f; bcol[s] = 0; }

    const uint32_t* AH = (const uint32_t*)(smf + W_AH);
    const uint32_t* ALp = (const uint32_t*)(smf + W_AL);
    const int aswz = ((g >> 2) & 1) << 2;
    const int w0 = kl ^ aswz, w1 = (kl + 4) ^ aswz;

    for (int t = 0; t < NTILES; t++) {
        CP_WAIT1();
        __syncthreads();
        const uint32_t* BH = (const uint32_t*)(smf + W_B + (t & 1) * 8192);
        const uint32_t* BL = BH + 4096;
        const float* cn = smf + W_CN + (t & 1) * 128 + wc * 64;

        float acc[2][8][4];
#pragma unroll
        for (int nf = 0; nf < 8; nf++) {
            float c0 = cn[nf * 8 + 2 * kl];
            float c1 = cn[nf * 8 + 2 * kl + 1];
#pragma unroll
            for (int m = 0; m < 2; m++) {
                acc[m][nf][0] = c0; acc[m][nf][1] = c1;
                acc[m][nf][2] = c0; acc[m][nf][3] = c1;
            }
        }
#pragma unroll
        for (int kc16 = 0; kc16 < 4; kc16++) {
            uint32_t ah[2][4], al[2][4];
#pragma unroll
            for (int m = 0; m < 2; m++) {
                int base = kc16 * 1024 + (wr * 32 + m * 16 + g) * 8;
                ah[m][0] = AH[base + w0];      ah[m][1] = AH[base + 64 + w0];
                ah[m][2] = AH[base + w1];      ah[m][3] = AH[base + 64 + w1];
                al[m][0] = ALp[base + w0];     al[m][1] = ALp[base + 64 + w0];
                al[m][2] = ALp[base + w1];     al[m][3] = ALp[base + 64 + w1];
            }
#pragma unroll
            for (int nf = 0; nf < 8; nf++) {
                int bb = kc16 * 1024 + (wc * 64 + nf * 8 + g) * 8;
                uint32_t bh0 = BH[bb + w0], bh1 = BH[bb + w1];
                uint32_t bl0 = BL[bb + w0], bl1 = BL[bb + w1];
#pragma unroll
                for (int m = 0; m < 2; m++) {
                    mma16(acc[m][nf], ah[m], bh0, bh1);
                    mma16(acc[m][nf], ah[m], bl0, bl1);
                    mma16(acc[m][nf], al[m], bh0, bh1);
                }
            }
        }
        // running per-slot argmax (ascending cols -> strict > keeps low index)
        int colbase0 = t * 128 + wc * 64 + 2 * kl;
#pragma unroll
        for (int m = 0; m < 2; m++) {
#pragma unroll
            for (int nf = 0; nf < 8; nf++) {
                int c01 = colbase0 + nf * 8;
                float v0 = acc[m][nf][0], v1 = acc[m][nf][1];
                float v2 = acc[m][nf][2], v3 = acc[m][nf][3];
                int s0 = 2 * m, s1 = 2 * m + 1;
                if (v0 > best[s0]) { best[s0] = v0; bcol[s0] = c01; }
                if (v1 > best[s0]) { best[s0] = v1; bcol[s0] = c01 + 1; }
                if (v2 > best[s1]) { best[s1] = v2; bcol[s1] = c01; }
                if (v3 > best[s1]) { best[s1] = v3; bcol[s1] = c01 + 1; }
            }
        }
        __syncthreads();
        if (t + 2 < NTILES) load_b_tile(smem_base, t + 2, tid);
        CP_COMMIT();
    }

    // ---- quad reduce ----
#pragma unroll
    for (int s = 0; s < 4; s++) {
        float v = best[s];
        int c = bcol[s];
#pragma unroll
        for (int off = 1; off <= 2; off <<= 1) {
            float ov = __shfl_xor_sync(0xffffffffu, v, off);
            int oc = __shfl_xor_sync(0xffffffffu, c, off);
            if (ov > v || (ov == v && oc < c)) { v = ov; c = oc; }
        }
        if ((lane & 3) == 0) {
            int rowl = wr * 32 + (s >> 1) * 16 + (s & 1) * 8 + g;
            RED[wc * 128 + rowl] = make_float2(v, __int_as_float(c));
        }
    }
    __syncthreads();

    // ---- exact fp32 rescore of the two half-winners per row ----
    if (tid < 128) {
        int row = tid, rg = row0 + row;
        float xv[64];
        const float4* ip = (const float4*)(input + (size_t)rg * 64);
        const float4* pp = (const float4*)(g_pe + (size_t)(rg & 1023) * 64);
#pragma unroll
        for (int q = 0; q < 16; q++) {
            float4 a = ip[q], b = pp[q];
            xv[q * 4 + 0] = a.x + b.x; xv[q * 4 + 1] = a.y + b.y;
            xv[q * 4 + 2] = a.z + b.z; xv[q * 4 + 3] = a.w + b.w;
        }
        int c0 = __float_as_int(RED[row].y);
        int c1 = __float_as_int(RED[128 + row].y);
        float s0 = g_cn[c0], s1 = g_cn[c1];
        const float4* e0 = (const float4*)(g_et + (size_t)c0 * 64);
        const float4* e1 = (const float4*)(g_et + (size_t)c1 * 64);
#pragma unroll
        for (int q = 0; q < 16; q++) {
            float4 ea = e0[q], eb = e1[q];
            s0 = fmaf(xv[q * 4 + 0], ea.x, s0); s0 = fmaf(xv[q * 4 + 1], ea.y, s0);
            s0 = fmaf(xv[q * 4 + 2], ea.z, s0); s0 = fmaf(xv[q * 4 + 3], ea.w, s0);
            s1 = fmaf(xv[q * 4 + 0], eb.x, s1); s1 = fmaf(xv[q * 4 + 1], eb.y, s1);
            s1 = fmaf(xv[q * 4 + 2], eb.z, s1); s1 = fmaf(xv[q * 4 + 3], eb.w, s1);
        }
        int bj = (s1 > s0 || (s1 == s0 && c1 < c0)) ? c1 : c0;
        IndSh[row] = bj;
        if (full) out[OFF_IND + rg] = (float)bj;
        atomicAdd(&g_counts[bj], 1.0f);
    }
    __syncthreads();

    // ---- epilogue: quantize gather, loss, embed_sum scatter (float2) ----
    {
        float lsum = 0.0f;
        const int k0 = 2 * lane;
        for (int it = 0; it < 16; it++) {
            int rloc = wid * 16 + it;
            int rg = row0 + rloc;
            int j = IndSh[rloc];
            float2 ev = *(const float2*)(g_et + (size_t)j * 64 + k0);
            float2 iv = *(const float2*)(input + (size_t)rg * 64 + k0);
            float2 pe = *(const float2*)(g_pe + (size_t)(rg & 1023) * 64 + k0);
            float d0 = ev.x - iv.x, d1 = ev.y - iv.y;
            lsum += d0 * d0 + d1 * d1;
            *(float2*)(out + OFF_Q + (size_t)rg * 64 + k0) = ev;
            atomicAdd(&g_esum[(size_t)k0 * NCODES + j], iv.x + pe.x);
            atomicAdd(&g_esum[(size_t)(k0 + 1) * NCODES + j], iv.y + pe.y);
        }
#pragma unroll
        for (int off = 16; off; off >>= 1)
            lsum += __shfl_down_sync(0xffffffffu, lsum, off);
        if (lane == 0) atomicAdd(smf + W_LOSS, lsum);
    }
    __syncthreads();
    if (tid == 0) atomicAdd(&g_loss, smf[W_LOSS]);
}

// ---------------------------------------------------------------------------
// fused finalize: new_cluster, new_embed_avg, new_embed, loss.
// grid 512 x 256 (float4 loads; scalar stores — out offsets are odd).
// ---------------------------------------------------------------------------
__global__ void vq_fin(const float* __restrict__ cs,
                       const float* __restrict__ ea,
                       float* __restrict__ out) {
    int i4 = blockIdx.x * 256 + threadIdx.x;    // 0..131071
    int idx = i4 * 4;
    float4 e4 = ((const float4*)ea)[i4];
    float4 s4 = ((const float4*)g_esum)[i4];
    float nea0 = 0.8f * e4.x + 0.2f * s4.x;
    float nea1 = 0.8f * e4.y + 0.2f * s4.y;
    float nea2 = 0.8f * e4.z + 0.2f * s4.z;
    float nea3 = 0.8f * e4.w + 0.2f * s4.w;
    out[OFF_EA + idx + 0] = nea0;
    out[OFF_EA + idx + 1] = nea1;
    out[OFF_EA + idx + 2] = nea2;
    out[OFF_EA + idx + 3] = nea3;

    int jb = (idx & (NCODES - 1)) >> 2;
    float4 c4 = ((const float4*)cs)[jb];
    float4 t4 = ((const float4*)g_counts)[jb];
    float nc0 = 0.8f * c4.x + 0.2f * t4.x;
    float nc1 = 0.8f * c4.y + 0.2f * t4.y;
    float nc2 = 0.8f * c4.z + 0.2f * t4.z;
    float nc3 = 0.8f * c4.w + 0.2f * t4.w;

    float total = g_total;
    float denom = total + NCODES * 1e-5f;
    float sc = total / denom;
    out[OFF_NE + idx + 0] = nea0 / ((nc0 + 1e-5f) * sc);
    out[OFF_NE + idx + 1] = nea1 / ((nc1 + 1e-5f) * sc);
    out[OFF_NE + idx + 2] = nea2 / ((nc2 + 1e-5f) * sc);
    out[OFF_NE + idx + 3] = nea3 / ((nc3 + 1e-5f) * sc);

    if (idx < NCODES) {
        out[OFF_NC + idx + 0] = nc0;
        out[OFF_NC + idx + 1] = nc1;
        out[OFF_NC + idx + 2] = nc2;
        out[OFF_NC + idx + 3] = nc3;
    }
    if (i4 == 0) out[OFF_LOSS] = g_loss * (1.0f / 2097152.0f);
}

// ---------------------------------------------------------------------------
extern "C" void kernel_launch(void* const* d_in, const int* in_sizes, int n_in,
                              void* d_out, int out_size) {
    const float* input = (const float*)d_in[0];
    const float* embed = (const float*)d_in[1];
    const float* pos   = (const float*)d_in[2];
    const float* cs    = (const float*)d_in[3];
    const float* ea    = (const float*)d_in[4];
    float* out = (float*)d_out;

    cudaFuncSetAttribute(vq_main, cudaFuncAttributeMaxDynamicSharedMemorySize,
                         SMEM_TOTAL);
    int full = (out_size >= OUT_FULL) ? 1 : 0;

    vq_prep0<<<512, 256>>>(pos, cs);
    vq_prep1<<<256, 256>>>(embed);
    vq_main<<<256, 256, SMEM_TOTAL>>>(input, out, full);
    if (full) vq_fin<<<512, 256>>>(cs, ea, out);
}

// round 16
// speedup vs baseline: 1.0429x; 1.0044x over previous
#include <cuda_runtime.h>
#include <cuda_fp16.h>
#include <cstdint>

// ---------------------------------------------------------------------------
// VectorQuantize via mma.sync.m16n8k16.f16 (3xFP16 emulated fp32) + exact
// fp32 rescore. vq_main = champion GEMM loop + float2 epilogue. PDL overlap:
// prep0 || prep1 (disjoint globals), and fin prefetches ea/cs during
// vq_main's rescore/epilogue tail (griddepcontrol).
// ---------------------------------------------------------------------------

#define NCODES 8192
#define OFF_Q     0
#define OFF_IND   2097152
#define OFF_LOSS  2129920
#define OFF_NC    2129921
#define OFF_EA    2138113
#define OFF_NE    2662401
#define OUT_FULL  3186689

#define RPB    128
#define NTILES 64

// smem word offsets
#define W_AH   0        // [4 kc16][128 row][8 w] fp16x2 words
#define W_AL   4096
#define W_B    8192     // 2 stages x (hi 4096 + lo 4096)
#define W_CN   24576    // 2 x 128
#define W_IND  24832
#define W_RED  24960    // 2 halves x 128 float2
#define W_LOSS 25472
#define SMEM_TOTAL 101920

#define PDL_TRIGGER() asm volatile("griddepcontrol.launch_dependents;" ::: "memory")
#define PDL_WAIT()    asm volatile("griddepcontrol.wait;" ::: "memory")

// device scratch
__device__ __align__(16) float g_pe[65536];
__device__ __align__(16) float g_cn[NCODES];
__device__ __align__(16) float g_counts[NCODES];
__device__ __align__(16) float g_esum[64 * NCODES];
__device__ __align__(16) float g_et[NCODES * 64];       // E^T fp32 [j][k]
__device__ __align__(16) uint32_t g_eh16[NCODES * 32];  // E^T fp16x2 hi [j][k/2]
__device__ __align__(16) uint32_t g_el16[NCODES * 32];  // E^T fp16x2 lo
__device__ float g_loss, g_total;

// ---------------------------------------------------------------------------
__device__ __forceinline__ uint32_t smem_u32(const void* p) {
    uint32_t a;
    asm("{ .reg .u64 t; cvta.to.shared.u64 t, %1; cvt.u32.u64 %0, t; }"
        : "=r"(a) : "l"(p));
    return a;
}
__device__ __forceinline__ void mma16(float* d, const uint32_t* a,
                                      uint32_t b0, uint32_t b1) {
    asm volatile(
        "mma.sync.aligned.m16n8k16.row.col.f32.f16.f16.f32 "
        "{%0,%1,%2,%3}, {%4,%5,%6,%7}, {%8,%9}, {%0,%1,%2,%3};"
        : "+f"(d[0]), "+f"(d[1]), "+f"(d[2]), "+f"(d[3])
        : "r"(a[0]), "r"(a[1]), "r"(a[2]), "r"(a[3]), "r"(b0), "r"(b1));
}
__device__ __forceinline__ void cp16(uint32_t dst, const void* src) {
    asm volatile("cp.async.cg.shared.global [%0], [%1], 16;"
                 :: "r"(dst), "l"(src) : "memory");
}
#define CP_COMMIT() asm volatile("cp.async.commit_group;" ::: "memory")
#define CP_WAIT1()  asm volatile("cp.async.wait_group 1;" ::: "memory")

__device__ __forceinline__ uint32_t pkh(float a, float b) {
    __half2 h = __floats2half2_rn(a, b);
    return *(uint32_t*)&h;
}

// ---------------------------------------------------------------------------
// prep0: float4 zero g_esum/g_counts, float4 PE build, cs-sum -> g_total.
// Triggers PDL immediately so prep1 overlaps. grid 512 x 256.
// ---------------------------------------------------------------------------
__global__ void vq_prep0(const float* __restrict__ pos_emb,
                         const float* __restrict__ cs) {
    PDL_TRIGGER();
    const int tid = threadIdx.x;
    int i4 = blockIdx.x * 256 + tid;            // 0..131071 float4 units
    float4 z = make_float4(0.f, 0.f, 0.f, 0.f);
    ((float4*)g_esum)[i4] = z;
    if (i4 < 16384) {
        int idx = i4 * 4;
        int j = idx & 63, i = (idx >> 6) & 63, c = idx >> 12;
        int s = ((i >> 2) << 4) + (j >> 2);
        int d = (c << 4) + ((i & 3) << 2);      // (j&3)==0
        ((float4*)g_pe)[i4] = *(const float4*)(pos_emb + s * 256 + d);
    }
    if (i4 < 2048) ((float4*)g_counts)[i4] = z;

    if (blockIdx.x == 0) {
        float ssum = 0.0f;
#pragma unroll
        for (int q = 0; q < 8; q++) {
            float4 v = ((const float4*)cs)[tid + q * 256];
            ssum += v.x + v.y + v.z + v.w;
        }
        __shared__ float sh[256];
        sh[tid] = ssum;
        __syncthreads();
        for (int s = 128; s; s >>= 1) {
            if (tid < s) sh[tid] += sh[tid + s];
            __syncthreads();
        }
        if (tid == 0) {
            g_total = 0.8f * sh[0] + 0.2f * 32768.0f;
            g_loss = 0.0f;
        }
    }
}

// ---------------------------------------------------------------------------
// prep1: transpose embed -> g_et, fp16 hi/lo splits, code norms.
// PDL-launched: overlaps prep0 (disjoint globals). grid 256 x 256.
// ---------------------------------------------------------------------------
__global__ void vq_prep1(const float* __restrict__ embed) {
    __shared__ float sE[64][33];
    __shared__ float scn[32][8];
    const int tid = threadIdx.x;
    const int j0 = blockIdx.x * 32;
#pragma unroll
    for (int pass = 0; pass < 8; pass++) {
        int k = pass * 8 + (tid >> 5);
        int jl = tid & 31;
        sE[k][jl] = embed[(size_t)k * NCODES + j0 + jl];
    }
    __syncthreads();
    const int jl = tid & 31, p = tid >> 5;
    const int j = j0 + jl;
    float ssum = 0.0f;
#pragma unroll
    for (int w = 0; w < 4; w++) {
        int k = p * 8 + 2 * w;
        float v0 = sE[k][jl], v1 = sE[k + 1][jl];
        ssum += v0 * v0 + v1 * v1;
        *(float2*)(g_et + (size_t)j * 64 + k) = make_float2(v0, v1);
        __half h0 = __float2half_rn(v0), h1 = __float2half_rn(v1);
        float l0 = v0 - __half2float(h0), l1 = v1 - __half2float(h1);
        g_eh16[(size_t)j * 32 + (k >> 1)] =
            pkh(__half2float(h0), __half2float(h1));
        g_el16[(size_t)j * 32 + (k >> 1)] = pkh(l0, l1);
    }
    scn[jl][p] = ssum;
    __syncthreads();
    if (tid < 32) {
        float s = 0.0f;
#pragma unroll
        for (int q = 0; q < 8; q++) s += scn[tid][q];
        g_cn[j0 + tid] = -0.5f * s;
    }
}

// ---------------------------------------------------------------------------
// async B tile: g_eh16/g_el16 [j][k/2] -> smem [kc16][col][w] swizzled
// ---------------------------------------------------------------------------
__device__ __forceinline__ void load_b_tile(uint32_t smem_base, int t, int tid) {
    const int cb = t * 128;
    const uint32_t bb = smem_base + (uint32_t)(W_B + (t & 1) * 8192) * 4u;
#pragma unroll
    for (int i = 0; i < 8; i++) {
        int c = tid + (i << 8);             // 0..2047
        int arr = c >> 10;                  // 0 hi, 1 lo
        int rem = c & 1023;
        int j = rem >> 3, ch = rem & 7;     // ch: 16B chunk within 128B row
        int kc16 = ch >> 1, half8 = ch & 1;
        const uint32_t* src = (arr ? g_el16 : g_eh16) + (size_t)(cb + j) * 32 + ch * 4;
        uint32_t dstw = (uint32_t)(arr * 4096 + kc16 * 1024 + j * 8 +
                                   ((half8 ^ ((j >> 2) & 1)) << 2));
        cp16(bb + dstw * 4u, src);
    }
    if (tid < 32)
        cp16(smem_base + (uint32_t)(W_CN + (t & 1) * 128) * 4u + tid * 16,
             g_cn + cb + tid * 4);
}

// ---------------------------------------------------------------------------
// main: 256 CTAs x 256 threads, 2 CTAs/SM. warp tile 32x64, 3xFP16 mma.
// Champion GEMM loop; float2 epilogue; PDL trigger after the GEMM loop so
// fin can prefetch during the rescore/epilogue tail.
// ---------------------------------------------------------------------------
__global__ void __launch_bounds__(256, 2)
vq_main(const float* __restrict__ input, float* __restrict__ out, int full) {
    extern __shared__ float smf[];
    const uint32_t smem_base = smem_u32(smf);
    const int tid = threadIdx.x, wid = tid >> 5, lane = tid & 31;
    const int wr = wid >> 1, wc = wid & 1;
    const int g = lane >> 2, kl = lane & 3;
    const int row0 = blockIdx.x * RPB;

    int* IndSh = (int*)(smf + W_IND);
    float2* RED = (float2*)(smf + W_RED);
    if (tid == 0) smf[W_LOSS] = 0.0f;

    // ---- A build: X = input + pe, fp16 hi/lo, fragment-native layout ----
    {
        int row = tid >> 1, h = tid & 1, rg = row0 + row;
        const float4* ip = (const float4*)(input + (size_t)rg * 64);
        const float4* pp = (const float4*)(g_pe + (size_t)(rg & 1023) * 64);
        int swz = ((row >> 2) & 1) << 2;
#pragma unroll
        for (int i = 0; i < 8; i++) {
            int q = h * 8 + i;
            int k0 = 4 * q, kc16 = k0 >> 4, o = k0 & 15, w = o >> 1;
            float4 a = ip[q], b = pp[q];
            float x0 = a.x + b.x, x1 = a.y + b.y;
            float x2 = a.z + b.z, x3 = a.w + b.w;
            __half h0 = __float2half_rn(x0), h1 = __float2half_rn(x1);
            __half h2 = __float2half_rn(x2), h3 = __float2half_rn(x3);
            float l0 = x0 - __half2float(h0), l1 = x1 - __half2float(h1);
            float l2 = x2 - __half2float(h2), l3 = x3 - __half2float(h3);
            int wsw = w ^ swz;
            int off = kc16 * 1024 + row * 8 + wsw;
            *(uint2*)(smf + W_AH + off) =
                make_uint2(pkh(__half2float(h0), __half2float(h1)),
                           pkh(__half2float(h2), __half2float(h3)));
            *(uint2*)(smf + W_AL + off) = make_uint2(pkh(l0, l1), pkh(l2, l3));
        }
    }
    load_b_tile(smem_base, 0, tid); CP_COMMIT();
    load_b_tile(smem_base, 1, tid); CP_COMMIT();

    float best[4];
    int bcol[4];
#pragma unroll
    for (int s = 0; s < 4; s++) { best[s] = -3.4e38f; bcol[s] = 0; }

    const uint32_t* AH = (const uint32_t*)(smf + W_AH);
    const uint32_t* ALp = (const uint32_t*)(smf + W_AL);
    const int aswz = ((g >> 2) & 1) << 2;
    const int w0 = kl ^ aswz, w1 = (kl + 4) ^ aswz;

    for (int t = 0; t < NTILES; t++) {
        CP_WAIT1();
        __syncthreads();
        const uint32_t* BH = (const uint32_t*)(smf + W_B + (t & 1) * 8192);
        const uint32_t* BL = BH + 4096;
        const float* cn = smf + W_CN + (t & 1) * 128 + wc * 64;

        float acc[2][8][4];
#pragma unroll
        for (int nf = 0; nf < 8; nf++) {
            float c0 = cn[nf * 8 + 2 * kl];
            float c1 = cn[nf * 8 + 2 * kl + 1];
#pragma unroll
            for (int m = 0; m < 2; m++) {
                acc[m][nf][0] = c0; acc[m][nf][1] = c1;
                acc[m][nf][2] = c0; acc[m][nf][3] = c1;
            }
        }
#pragma unroll
        for (int kc16 = 0; kc16 < 4; kc16++) {
            uint32_t ah[2][4], al[2][4];
#pragma unroll
            for (int m = 0; m < 2; m++) {
                int base = kc16 * 1024 + (wr * 32 + m * 16 + g) * 8;
                ah[m][0] = AH[base + w0];      ah[m][1] = AH[base + 64 + w0];
                ah[m][2] = AH[base + w1];      ah[m][3] = AH[base + 64 + w1];
                al[m][0] = ALp[base + w0];     al[m][1] = ALp[base + 64 + w0];
                al[m][2] = ALp[base + w1];     al[m][3] = ALp[base + 64 + w1];
            }
#pragma unroll
            for (int nf = 0; nf < 8; nf++) {
                int bb = kc16 * 1024 + (wc * 64 + nf * 8 + g) * 8;
                uint32_t bh0 = BH[bb + w0], bh1 = BH[bb + w1];
                uint32_t bl0 = BL[bb + w0], bl1 = BL[bb + w1];
#pragma unroll
                for (int m = 0; m < 2; m++) {
                    mma16(acc[m][nf], ah[m], bh0, bh1);
                    mma16(acc[m][nf], ah[m], bl0, bl1);
                    mma16(acc[m][nf], al[m], bh0, bh1);
                }
            }
        }
        // running per-slot argmax (ascending cols -> strict > keeps low index)
        int colbase0 = t * 128 + wc * 64 + 2 * kl;
#pragma unroll
        for (int m = 0; m < 2; m++) {
#pragma unroll
            for (int nf = 0; nf < 8; nf++) {
                int c01 = colbase0 + nf * 8;
                float v0 = acc[m][nf][0], v1 = acc[m][nf][1];
                float v2 = acc[m][nf][2], v3 = acc[m][nf][3];
                int s0 = 2 * m, s1 = 2 * m + 1;
                if (v0 > best[s0]) { best[s0] = v0; bcol[s0] = c01; }
                if (v1 > best[s0]) { best[s0] = v1; bcol[s0] = c01 + 1; }
                if (v2 > best[s1]) { best[s1] = v2; bcol[s1] = c01; }
                if (v3 > best[s1]) { best[s1] = v3; bcol[s1] = c01 + 1; }
            }
        }
        __syncthreads();
        if (t + 2 < NTILES) load_b_tile(smem_base, t + 2, tid);
        CP_COMMIT();
    }

    // GEMM done: let fin launch and prefetch its independent inputs.
    PDL_TRIGGER();

    // ---- quad reduce ----
#pragma unroll
    for (int s = 0; s < 4; s++) {
        float v = best[s];
        int c = bcol[s];
#pragma unroll
        for (int off = 1; off <= 2; off <<= 1) {
            float ov = __shfl_xor_sync(0xffffffffu, v, off);
            int oc = __shfl_xor_sync(0xffffffffu, c, off);
            if (ov > v || (ov == v && oc < c)) { v = ov; c = oc; }
        }
        if ((lane & 3) == 0) {
            int rowl = wr * 32 + (s >> 1) * 16 + (s & 1) * 8 + g;
            RED[wc * 128 + rowl] = make_float2(v, __int_as_float(c));
        }
    }
    __syncthreads();

    // ---- exact fp32 rescore of the two half-winners per row ----
    if (tid < 128) {
        int row = tid, rg = row0 + row;
        float xv[64];
        const float4* ip = (const float4*)(input + (size_t)rg * 64);
        const float4* pp = (const float4*)(g_pe + (size_t)(rg & 1023) * 64);
#pragma unroll
        for (int q = 0; q < 16; q++) {
            float4 a = ip[q], b = pp[q];
            xv[q * 4 + 0] = a.x + b.x; xv[q * 4 + 1] = a.y + b.y;
            xv[q * 4 + 2] = a.z + b.z; xv[q * 4 + 3] = a.w + b.w;
        }
        int c0 = __float_as_int(RED[row].y);
        int c1 = __float_as_int(RED[128 + row].y);
        float s0 = g_cn[c0], s1 = g_cn[c1];
        const float4* e0 = (const float4*)(g_et + (size_t)c0 * 64);
        const float4* e1 = (const float4*)(g_et + (size_t)c1 * 64);
#pragma unroll
        for (int q = 0; q < 16; q++) {
            float4 ea = e0[q], eb = e1[q];
            s0 = fmaf(xv[q * 4 + 0], ea.x, s0); s0 = fmaf(xv[q * 4 + 1], ea.y, s0);
            s0 = fmaf(xv[q * 4 + 2], ea.z, s0); s0 = fmaf(xv[q * 4 + 3], ea.w, s0);
            s1 = fmaf(xv[q * 4 + 0], eb.x, s1); s1 = fmaf(xv[q * 4 + 1], eb.y, s1);
            s1 = fmaf(xv[q * 4 + 2], eb.z, s1); s1 = fmaf(xv[q * 4 + 3], eb.w, s1);
        }
        int bj = (s1 > s0 || (s1 == s0 && c1 < c0)) ? c1 : c0;
        IndSh[row] = bj;
        if (full) out[OFF_IND + rg] = (float)bj;
        atomicAdd(&g_counts[bj], 1.0f);
    }
    __syncthreads();

    // ---- epilogue: quantize gather, loss, embed_sum scatter (float2) ----
    {
        float lsum = 0.0f;
        const int k0 = 2 * lane;
        for (int it = 0; it < 16; it++) {
            int rloc = wid * 16 + it;
            int rg = row0 + rloc;
            int j = IndSh[rloc];
            float2 ev = *(const float2*)(g_et + (size_t)j * 64 + k0);
            float2 iv = *(const float2*)(input + (size_t)rg * 64 + k0);
            float2 pe = *(const float2*)(g_pe + (size_t)(rg & 1023) * 64 + k0);
            float d0 = ev.x - iv.x, d1 = ev.y - iv.y;
            lsum += d0 * d0 + d1 * d1;
            *(float2*)(out + OFF_Q + (size_t)rg * 64 + k0) = ev;
            atomicAdd(&g_esum[(size_t)k0 * NCODES + j], iv.x + pe.x);
            atomicAdd(&g_esum[(size_t)(k0 + 1) * NCODES + j], iv.y + pe.y);
        }
#pragma unroll
        for (int off = 16; off; off >>= 1)
            lsum += __shfl_down_sync(0xffffffffu, lsum, off);
        if (lane == 0) atomicAdd(smf + W_LOSS, lsum);
    }
    __syncthreads();
    if (tid == 0) atomicAdd(&g_loss, smf[W_LOSS]);
}

// ---------------------------------------------------------------------------
// fused finalize (PDL): prefetch ea/cs before griddepcontrol.wait, then read
// vq_main's g_esum/g_counts/g_loss. grid 512 x 256.
// ---------------------------------------------------------------------------
__global__ void vq_fin(const float* __restrict__ cs,
                       const float* __restrict__ ea,
                       float* __restrict__ out) {
    int i4 = blockIdx.x * 256 + threadIdx.x;    // 0..131071
    int idx = i4 * 4;
    // independent inputs: issue before waiting on vq_main
    float4 e4 = ((const float4*)ea)[i4];
    int jb = (idx & (NCODES - 1)) >> 2;
    float4 c4 = ((const float4*)cs)[jb];

    PDL_WAIT();   // vq_main fully complete: g_esum/g_counts/g_loss final

    float4 s4 = ((const float4*)g_esum)[i4];
    float4 t4 = ((const float4*)g_counts)[jb];
    float nea0 = 0.8f * e4.x + 0.2f * s4.x;
    float nea1 = 0.8f * e4.y + 0.2f * s4.y;
    float nea2 = 0.8f * e4.z + 0.2f * s4.z;
    float nea3 = 0.8f * e4.w + 0.2f * s4.w;
    out[OFF_EA + idx + 0] = nea0;
    out[OFF_EA + idx + 1] = nea1;
    out[OFF_EA + idx + 2] = nea2;
    out[OFF_EA + idx + 3] = nea3;

    float nc0 = 0.8f * c4.x + 0.2f * t4.x;
    float nc1 = 0.8f * c4.y + 0.2f * t4.y;
    float nc2 = 0.8f * c4.z + 0.2f * t4.z;
    float nc3 = 0.8f * c4.w + 0.2f * t4.w;

    float total = g_total;
    float denom = total + NCODES * 1e-5f;
    float sc = total / denom;
    out[OFF_NE + idx + 0] = nea0 / ((nc0 + 1e-5f) * sc);
    out[OFF_NE + idx + 1] = nea1 / ((nc1 + 1e-5f) * sc);
    out[OFF_NE + idx + 2] = nea2 / ((nc2 + 1e-5f) * sc);
    out[OFF_NE + idx + 3] = nea3 / ((nc3 + 1e-5f) * sc);

    if (idx < NCODES) {
        out[OFF_NC + idx + 0] = nc0;
        out[OFF_NC + idx + 1] = nc1;
        out[OFF_NC + idx + 2] = nc2;
        out[OFF_NC + idx + 3] = nc3;
    }
    if (i4 == 0) out[OFF_LOSS] = g_loss * (1.0f / 2097152.0f);
}

// ---------------------------------------------------------------------------
extern "C" void kernel_launch(void* const* d_in, const int* in_sizes, int n_in,
                              void* d_out, int out_size) {
    const float* input = (const float*)d_in[0];
    const float* embed = (const float*)d_in[1];
    const float* pos   = (const float*)d_in[2];
    const float* cs    = (const float*)d_in[3];
    const float* ea    = (const float*)d_in[4];
    float* out = (float*)d_out;

    cudaFuncSetAttribute(vq_main, cudaFuncAttributeMaxDynamicSharedMemorySize,
                         SMEM_TOTAL);
    int full = (out_size >= OUT_FULL) ? 1 : 0;

    cudaLaunchAttribute pdl[1];
    pdl[0].id = cudaLaunchAttributeProgrammaticStreamSerialization;
    pdl[0].val.programmaticStreamSerializationAllowed = 1;

    // prep0 (normal; triggers at entry) || prep1 (PDL)
    vq_prep0<<<512, 256>>>(pos, cs);
    {
        cudaLaunchConfig_t cfg = {};
        cfg.gridDim = dim3(256, 1, 1);
        cfg.blockDim = dim3(256, 1, 1);
        cfg.dynamicSmemBytes = 0;
        cfg.stream = 0;
        cfg.attrs = pdl;
        cfg.numAttrs = 1;
        cudaLaunchKernelEx(&cfg, vq_prep1, embed);
    }
    // vq_main: normal launch -> stream-ordered after both preps
    vq_main<<<256, 256, SMEM_TOTAL>>>(input, out, full);
    if (full) {
        cudaLaunchConfig_t cfg = {};
        cfg.gridDim = dim3(512, 1, 1);
        cfg.blockDim = dim3(256, 1, 1);
        cfg.dynamicSmemBytes = 0;
        cfg.stream = 0;
        cfg.attrs = pdl;
        cfg.numAttrs = 1;
        cudaLaunchKernelEx(&cfg, vq_fin, cs, ea, out);
    }
}